// round 11
// baseline (speedup 1.0000x reference)
#include <cuda_runtime.h>
#include <cuda_bf16.h>
#include <cuda_fp16.h>
#include <cstdint>

#define PRED  96
#define SEQ   512
#define NCH   321
#define NB    64
#define KTOT  608
#define NDICT 2000
#define NCOL  20544
#define KC    32
#define NCHUNK 19          // 608 / 32 exact
#define NTILES 321         // 20544 / 64 exact

// ---------------- device scratch ----------------
__device__ float g_bias[PRED];
__device__ float g_B[192 * KTOT];       // [j][col]
__device__ float g_Ax[192 * PRED];      // [j][p]
__device__ float g_Ar[192 * PRED];      // [j][p]
// W in mma-fragment layout, fp16: [chunk19][kt2][nt12][lane32][reg2] pairs
__device__ uint16_t g_Bf[NCHUNK * 3072];

__device__ __forceinline__ void qmap(int q, int &i, int &g, int &dim, int &qq) {
    if (q < 24)      { i = 0; g = 4;  dim = 24; qq = q;      }
    else if (q < 36) { i = 1; g = 8;  dim = 12; qq = q - 24; }
    else if (q < 44) { i = 2; g = 12; dim = 8;  qq = q - 36; }
    else             { i = 3; g = 24; dim = 4;  qq = q - 44; }
}

// ---------------- asm helpers ----------------
__device__ __forceinline__ uint32_t pack_f16x2(float lo, float hi) {
    uint32_t r;
    asm("cvt.rn.f16x2.f32 %0, %1, %2;" : "=r"(r) : "f"(hi), "f"(lo));
    return r;
}
__device__ __forceinline__ void sts128(uint32_t a, uint32_t v0, uint32_t v1,
                                       uint32_t v2, uint32_t v3) {
    asm volatile("st.shared.v4.b32 [%0], {%1,%2,%3,%4};"
                 :: "r"(a), "r"(v0), "r"(v1), "r"(v2), "r"(v3));
}
__device__ __forceinline__ void cpa16(uint32_t d, const void* s) {
    asm volatile("cp.async.cg.shared.global [%0], [%1], 16;" :: "r"(d), "l"(s));
}
__device__ __forceinline__ void cp_commit() { asm volatile("cp.async.commit_group;"); }
__device__ __forceinline__ void cp_wait2()  { asm volatile("cp.async.wait_group 2;" ::: "memory"); }

__device__ __forceinline__ void ldmat4(uint32_t &a0, uint32_t &a1, uint32_t &a2,
                                       uint32_t &a3, uint32_t addr) {
    asm volatile("ldmatrix.sync.aligned.m8n8.x4.shared.b16 {%0,%1,%2,%3}, [%4];"
                 : "=r"(a0), "=r"(a1), "=r"(a2), "=r"(a3) : "r"(addr));
}
__device__ __forceinline__ void lds64(uint32_t &b0, uint32_t &b1, uint32_t addr) {
    asm volatile("ld.shared.v2.b32 {%0,%1}, [%2];" : "=r"(b0), "=r"(b1) : "r"(addr));
}
__device__ __forceinline__ void mma16816(float* d, uint32_t a0, uint32_t a1,
                                         uint32_t a2, uint32_t a3,
                                         uint32_t b0, uint32_t b1) {
    asm volatile(
        "mma.sync.aligned.m16n8k16.row.col.f32.f16.f16.f32 "
        "{%0,%1,%2,%3}, {%4,%5,%6,%7}, {%8,%9}, {%0,%1,%2,%3};"
        : "+f"(d[0]), "+f"(d[1]), "+f"(d[2]), "+f"(d[3])
        : "r"(a0), "r"(a1), "r"(a2), "r"(a3), "r"(b0), "r"(b1));
}

// ================= k_prep =================
// blocks 0..191: band rows of g_B
// blocks 192..287: bias
// blocks 288..291: coalesced transpose of wf halves into g_Ax / g_Ar
__global__ void k_prep(const float* __restrict__ wxs, const float* __restrict__ wxt,
    const float* __restrict__ wfs, const float* __restrict__ wft,
    const float* __restrict__ rws0, const float* __restrict__ rws1,
    const float* __restrict__ rws2, const float* __restrict__ rws3,
    const float* __restrict__ rwt0, const float* __restrict__ rwt1,
    const float* __restrict__ rwt2, const float* __restrict__ rwt3,
    const float* __restrict__ bxs,  const float* __restrict__ bxt,
    const float* __restrict__ bfs,  const float* __restrict__ bft,
    const float* __restrict__ rbs0, const float* __restrict__ rbs1,
    const float* __restrict__ rbs2, const float* __restrict__ rbs3,
    const float* __restrict__ rbt0, const float* __restrict__ rbt1,
    const float* __restrict__ rbt2, const float* __restrict__ rbt3) {
    int tid = threadIdx.x;
    if (blockIdx.x >= 288) {
        __shared__ float sm[96][97];
        int b2 = blockIdx.x - 288;
        int side = b2 >> 1, half = b2 & 1;
        const float* wf = side ? wft : wfs;
        float* dst = half ? g_Ar : g_Ax;
        for (int idx = tid; idx < 96 * 96; idx += blockDim.x) {
            int p = idx / 96, r = idx - p * 96;
            sm[p][r] = wf[p * 192 + half * 96 + r];
        }
        __syncthreads();
        for (int idx = tid; idx < 96 * 96; idx += blockDim.x) {
            int r = idx / 96, p = idx - r * 96;
            dst[(side * 96 + r) * 96 + p] = sm[p][r];
        }
        return;
    }
    if (blockIdx.x >= 192) {
        __shared__ float red[8];
        int p = blockIdx.x - 192;
        float c = 0.f;
        if (tid < 96) {
            int j = tid;
            c = wfs[p * 192 + j] * bxs[j] + wft[p * 192 + j] * bxt[j]
              + wfs[p * 192 + 96 + j] * (rbs0[j] + rbs1[j] + rbs2[j] + rbs3[j])
              + wft[p * 192 + 96 + j] * (rbt0[j] + rbt1[j] + rbt2[j] + rbt3[j]);
        }
        for (int o = 16; o; o >>= 1) c += __shfl_down_sync(0xffffffffu, c, o);
        if ((tid & 31) == 0) red[tid >> 5] = c;
        __syncthreads();
        if (tid == 0) {
            float s = bfs[p] + bft[p];
            #pragma unroll
            for (int i = 0; i < 4; ++i) s += red[i];
            g_bias[p] = s;
        }
        return;
    }
    __shared__ float r[512];
    __shared__ float red[8];
    __shared__ float s_su;
    int j = blockIdx.x;
    int side = j / 96, row = j % 96;
    const float* wx = side ? wxt : wxs;
    r[tid]       = wx[row * SEQ + tid];
    r[tid + 256] = wx[row * SEQ + tid + 256];
    __syncthreads();
    {
        float a = r[tid] + r[tid + 256];
        for (int o = 16; o; o >>= 1) a += __shfl_down_sync(0xffffffffu, a, o);
        if ((tid & 31) == 0) red[tid >> 5] = a;
        __syncthreads();
        if (tid == 0) {
            float s = 0.f;
            #pragma unroll
            for (int i = 0; i < 8; ++i) s += red[i];
            s_su = s;
        }
        __syncthreads();
    }
    float su = s_su;
    #pragma unroll
    for (int t = 0; t < 2; ++t) {
        int l = tid + t * 256;
        int lo = (l - 12 < 0) ? 0 : l - 12;
        int hi = (l + 12 > 511) ? 511 : l + 12;
        float band = 0.f;
        for (int m = lo; m <= hi; ++m) {
            float cnt = 1.f;
            if (l == 0)   cnt = (float)(13 - m);
            if (l == 511) cnt = (float)(m - 498);
            band += cnt * r[m];
        }
        band *= 0.04f;
        float v = side ? band : (r[l] - band);
        float ml = 0.f;
        if (l >= 499 && l <= 510) ml = 0.04f;
        if (l == 511)             ml = 0.52f;
        float coef = side ? (-ml) : (ml - (l == 511 ? 1.f : 0.f));
        v += su * coef;
        g_B[j * KTOT + l] = v;
    }
    if (tid < 96) {
        int q = tid;
        int i, g, dim, qq; qmap(q % 48, i, g, dim, qq);
        float rv = 0.f;
        if ((q / 48) == side) {
            const float* rw;
            if (!side) rw = (i == 0) ? rws0 : (i == 1) ? rws1 : (i == 2) ? rws2 : rws3;
            else       rw = (i == 0) ? rwt0 : (i == 1) ? rwt1 : (i == 2) ? rwt2 : rwt3;
            rv = rw[row * dim + qq];
        }
        g_B[j * KTOT + 512 + q] = rv;
    }
}

// ================= k_pgemm (validated fragment layout) =================
__global__ __launch_bounds__(128) void k_pgemm() {
    __shared__ float sA[32 * 96];
    __shared__ float sB[32][8];
    int tid = threadIdx.x;
    int tp = tid >> 2;
    int tc = tid & 3;
    int col0 = blockIdx.x * 8;
    const float* A = (col0 >= 512) ? g_Ar : g_Ax;
    float acc[3][2] = {};
    for (int jc = 0; jc < 6; ++jc) {
        __syncthreads();
        const float4* srcA = reinterpret_cast<const float4*>(A + jc * 32 * 96);
        #pragma unroll
        for (int i = 0; i < 6; ++i)
            reinterpret_cast<float4*>(sA)[tid + i * 128] = srcA[tid + i * 128];
        #pragma unroll
        for (int i = 0; i < 2; ++i) {
            int idx = tid + i * 128;
            int jj = idx >> 3, cc = idx & 7;
            sB[jj][cc] = g_B[(jc * 32 + jj) * KTOT + col0 + cc];
        }
        __syncthreads();
        #pragma unroll 8
        for (int jj = 0; jj < 32; ++jj) {
            float b0 = sB[jj][tc * 2], b1 = sB[jj][tc * 2 + 1];
            #pragma unroll
            for (int u = 0; u < 3; ++u) {
                float a = sA[jj * 96 + tp * 3 + u];
                acc[u][0] += a * b0;
                acc[u][1] += a * b1;
            }
        }
    }
    #pragma unroll
    for (int v = 0; v < 2; ++v) {
        int col = col0 + tc * 2 + v;
        float add = (col == 511) ? 1.f : 0.f;
        #pragma unroll
        for (int u = 0; u < 3; ++u) {
            float val = acc[u][v] + add;
            int p = tp * 3 + u;
            __half hv = __float2half(val);
            int lane = (p & 7) * 4 + ((col & 7) >> 1);
            int reg  = (col >> 3) & 1;
            long off = ((((long)(col >> 5) * 2 + ((col >> 4) & 1)) * 12 + (p >> 3)) * 32
                        + lane) * 8 + reg * 4 + (col & 1) * 2;
            *(uint16_t*)((char*)g_Bf + off) = __half_as_ushort(hv);
        }
    }
}

// ================= k_main: fp16 HMMA, 2-deep register staging =================
// LDGA at loop top, STSA at loop bottom -> LDG->use distance ~2 iterations;
// residual stalls overlap with tensor-pipe drain.
__global__ __launch_bounds__(256, 3) void k_main(
    const float* __restrict__ x, const float* __restrict__ rds,
    const float* __restrict__ rdt, const int* __restrict__ index,
    float* __restrict__ out) {
    __shared__ int sxb[64], sdb[64], sob[64];
    __shared__ const float* qptr[96];
    __shared__ float sbias[96];
    extern __shared__ char dsm_raw[];

    int tid = threadIdx.x;
    int wid = tid >> 5, lane = tid & 31;
    int j0 = blockIdx.x * 64;

    if (tid < 64) {
        int jj = j0 + tid;
        int b = jj / NCH, c = jj - b * NCH;
        sxb[tid] = b * SEQ * NCH + c;
        sob[tid] = b * PRED * NCH + c;
        sdb[tid] = index[b] * PRED * NCH + c;
    }
    if (tid < 96) {
        int q = tid;
        int i, g, dim, qq; qmap(q % 48, i, g, dim, qq);
        const float* base = (q < 48) ? rds : rdt;
        qptr[q] = base + (size_t)i * (NDICT * PRED * NCH) + (size_t)qq * g * NCH;
        sbias[tid] = g_bias[tid];
    }
    __syncthreads();

    uint32_t db = (uint32_t)__cvta_generic_to_shared(dsm_raw);
    uint32_t ab = (db + 127u) & ~127u;
    uint32_t AF[3] = { ab, ab + 5120, ab + 10240 };           // 64 rows x 80B
    uint32_t BF[4] = { ab + 15360, ab + 21504, ab + 27648, ab + 33792 };

    int m  = tid & 63;           // producer column
    int kh = tid >> 6;           // 0..3: k-octet of chunk
    const float* xcol = x + sxb[m];
    int dcol = sdb[m];
    uint32_t arow_off = (uint32_t)(m * 80 + kh * 16);

    int mw = wid & 3;            // m-tile (16 rows)
    int ng = wid >> 2;           // n-group: nt 6*ng .. 6*ng+5
    uint32_t aoff = (uint32_t)((mw * 16 + (lane & 7) + ((lane >> 3) & 1) * 8) * 80
                               + ((lane >> 4) & 1) * 16);
    uint32_t boff = (uint32_t)(ng * 6 * 256 + lane * 8);

    float acc[6][4];
    #pragma unroll
    for (int nt = 0; nt < 6; ++nt)
        #pragma unroll
        for (int v = 0; v < 4; ++v) acc[nt][v] = 0.f;

    float vb[2][8];              // 2-deep register staging for A

    #define LDGA(cc, rb) do {                                                \
        int _k0 = (cc) * KC + kh * 8;                                        \
        if (_k0 < 512) {                                                     \
            const float* _s = xcol + (size_t)_k0 * NCH;                      \
            _Pragma("unroll")                                                \
            for (int i_ = 0; i_ < 8; ++i_) vb[rb][i_] = _s[i_ * NCH];        \
        } else {                                                             \
            int _q0 = _k0 - 512;                                             \
            _Pragma("unroll")                                                \
            for (int i_ = 0; i_ < 8; ++i_) vb[rb][i_] = qptr[_q0 + i_][dcol];\
        }                                                                    \
    } while (0)

    #define STSA(abuf, rb) do {                                              \
        uint32_t h_[4];                                                      \
        _Pragma("unroll")                                                    \
        for (int t_ = 0; t_ < 4; ++t_)                                       \
            h_[t_] = pack_f16x2(vb[rb][2 * t_], vb[rb][2 * t_ + 1]);         \
        sts128(AF[abuf] + arow_off, h_[0], h_[1], h_[2], h_[3]);             \
    } while (0)

    #define FILLB(bbuf, cc) do {                                             \
        const char* _sf = (const char*)g_Bf + (size_t)(cc) * 6144;           \
        if (tid < 192) {                                                     \
            uint32_t off = (uint32_t)tid * 16u;                              \
            cpa16(BF[bbuf] + off, _sf + off);                                \
            cpa16(BF[bbuf] + off + 3072, _sf + off + 3072);                  \
        }                                                                    \
    } while (0)

    // prologue: A[0] staged now (one exposed stall); vb[1] holds chunk 1.
    LDGA(0, 0); STSA(0, 0);
    LDGA(1, 1);
    FILLB(0, 0); cp_commit();
    FILLB(1, 1); cp_commit();

    #pragma unroll 1
    for (int c = 0; c < NCHUNK; ++c) {
        int ac = c % 3;                    // A buffer holding chunk c
        int bc = c & 3;                    // B buffer holding chunk c
        // top: issue next-next loads early (consumed 2 iterations later)
        if (c + 2 < NCHUNK) {
            LDGA(c + 2, c & 1);            // vb[c&1]: freed at bottom of iter c-1
            FILLB((c + 2) & 3, c + 2);
        }
        cp_commit();                       // uniform group count
        cp_wait2();                        // B(c) arrived
        __syncthreads();                   // A(c) (written bottom of c-1) visible

        #pragma unroll
        for (int kt = 0; kt < 2; ++kt) {
            uint32_t a0, a1, a2, a3;
            ldmat4(a0, a1, a2, a3, AF[ac] + aoff + kt * 32);
            uint32_t bb = BF[bc] + (uint32_t)(kt * 3072) + boff;
            #pragma unroll
            for (int nt = 0; nt < 6; ++nt) {
                uint32_t b0, b1;
                lds64(b0, b1, bb + nt * 256);
                mma16816(acc[nt], a0, a1, a2, a3, b0, b1);
            }
        }
        // bottom: stage A(c+1) from registers loaded in iter c-1
        if (c + 1 < NCHUNK) STSA((c + 1) % 3, (c + 1) & 1);
    }
    #undef LDGA
    #undef STSA
    #undef FILLB

    // ---- epilogue ----
    int g = lane >> 2, tg = lane & 3;
    int r0 = mw * 16 + g, r1 = r0 + 8;
    int ob0 = sob[r0], ob1 = sob[r1];
    #pragma unroll
    for (int nt = 0; nt < 6; ++nt) {
        int p0 = (ng * 6 + nt) * 8 + tg * 2;
        float sb0 = sbias[p0], sb1 = sbias[p0 + 1];
        out[ob0 + p0 * NCH]       = acc[nt][0] + sb0;
        out[ob0 + (p0 + 1) * NCH] = acc[nt][1] + sb1;
        out[ob1 + p0 * NCH]       = acc[nt][2] + sb0;
        out[ob1 + (p0 + 1) * NCH] = acc[nt][3] + sb1;
    }
}

// ---------------- launch ----------------
#define DSM_BYTES (39936 + 256)

extern "C" void kernel_launch(void* const* d_in, const int* in_sizes, int n_in,
                              void* d_out, int out_size) {
    const float* x   = (const float*)d_in[0];
    const int*   idx = (const int*)d_in[1];
    const float* rds = (const float*)d_in[2];
    const float* rdt = (const float*)d_in[3];
    const float* wxs = (const float*)d_in[4];
    const float* bxs = (const float*)d_in[5];
    const float* wxt = (const float*)d_in[6];
    const float* bxt = (const float*)d_in[7];

    const float *wfs, *bfs, *wft, *bft;
    const float *rws[4], *rbs[4], *rwt[4], *rbt[4];

    if (in_sizes[8] == PRED * 2 * PRED) {
        wfs = (const float*)d_in[8];  bfs = (const float*)d_in[9];
        wft = (const float*)d_in[10]; bft = (const float*)d_in[11];
        for (int i = 0; i < 4; ++i) {
            rws[i] = (const float*)d_in[12 + 4 * i];
            rbs[i] = (const float*)d_in[13 + 4 * i];
            rwt[i] = (const float*)d_in[14 + 4 * i];
            rbt[i] = (const float*)d_in[15 + 4 * i];
        }
    } else {
        for (int i = 0; i < 4; ++i) {
            rws[i] = (const float*)d_in[8 + i];
            rbs[i] = (const float*)d_in[12 + i];
            rwt[i] = (const float*)d_in[16 + i];
            rbt[i] = (const float*)d_in[20 + i];
        }
        wfs = (const float*)d_in[24]; bfs = (const float*)d_in[25];
        wft = (const float*)d_in[26]; bft = (const float*)d_in[27];
    }

    float* out = (float*)d_out;

    cudaFuncSetAttribute(k_main, cudaFuncAttributeMaxDynamicSharedMemorySize,
                         DSM_BYTES);

    k_prep<<<292, 256>>>(wxs, wxt, wfs, wft,
                         rws[0], rws[1], rws[2], rws[3],
                         rwt[0], rwt[1], rwt[2], rwt[3],
                         bxs, bxt, bfs, bft,
                         rbs[0], rbs[1], rbs[2], rbs[3],
                         rbt[0], rbt[1], rbt[2], rbt[3]);
    k_pgemm<<<76, 128>>>();
    k_main<<<NTILES, 256, DSM_BYTES>>>(x, rds, rdt, idx, out);
}

// round 12
// speedup vs baseline: 1.2066x; 1.2066x over previous
#include <cuda_runtime.h>
#include <cuda_bf16.h>
#include <cuda_fp16.h>
#include <cstdint>

#define PRED  96
#define SEQ   512
#define NCH   321
#define NB    64
#define KTOT  608
#define NDICT 2000
#define NCOL  20544
#define KC    32
#define NCHUNK 19          // 608 / 32 exact
#define NTILES 321         // 20544 / 64 exact

// ---------------- device scratch ----------------
__device__ float g_bias[PRED];
__device__ float g_B[192 * KTOT];       // [j][col]
__device__ float g_Ax[192 * PRED];      // [j][p]
__device__ float g_Ar[192 * PRED];      // [j][p]
// W in mma-fragment layout, fp16: [chunk19][kt2][nt12][lane32][reg2] pairs
__device__ uint16_t g_Bf[NCHUNK * 3072];

__device__ __forceinline__ void qmap(int q, int &i, int &g, int &dim, int &qq) {
    if (q < 24)      { i = 0; g = 4;  dim = 24; qq = q;      }
    else if (q < 36) { i = 1; g = 8;  dim = 12; qq = q - 24; }
    else if (q < 44) { i = 2; g = 12; dim = 8;  qq = q - 36; }
    else             { i = 3; g = 24; dim = 4;  qq = q - 44; }
}

// ---------------- asm helpers ----------------
__device__ __forceinline__ uint32_t pack_f16x2(float lo, float hi) {
    uint32_t r;
    asm("cvt.rn.f16x2.f32 %0, %1, %2;" : "=r"(r) : "f"(hi), "f"(lo));
    return r;
}
__device__ __forceinline__ void sts128(uint32_t a, uint32_t v0, uint32_t v1,
                                       uint32_t v2, uint32_t v3) {
    asm volatile("st.shared.v4.b32 [%0], {%1,%2,%3,%4};"
                 :: "r"(a), "r"(v0), "r"(v1), "r"(v2), "r"(v3));
}
__device__ __forceinline__ void cpa16(uint32_t d, const void* s) {
    asm volatile("cp.async.cg.shared.global [%0], [%1], 16;" :: "r"(d), "l"(s));
}
__device__ __forceinline__ void cp_commit() { asm volatile("cp.async.commit_group;"); }
__device__ __forceinline__ void cp_wait2()  { asm volatile("cp.async.wait_group 2;" ::: "memory"); }

__device__ __forceinline__ void ldmat4(uint32_t &a0, uint32_t &a1, uint32_t &a2,
                                       uint32_t &a3, uint32_t addr) {
    asm volatile("ldmatrix.sync.aligned.m8n8.x4.shared.b16 {%0,%1,%2,%3}, [%4];"
                 : "=r"(a0), "=r"(a1), "=r"(a2), "=r"(a3) : "r"(addr));
}
__device__ __forceinline__ void lds64(uint32_t &b0, uint32_t &b1, uint32_t addr) {
    asm volatile("ld.shared.v2.b32 {%0,%1}, [%2];" : "=r"(b0), "=r"(b1) : "r"(addr));
}
// fp16-accumulate HMMA: full-rate (512 MAC/cyc/SM)
__device__ __forceinline__ void mma16816h(uint32_t* d, uint32_t a0, uint32_t a1,
                                          uint32_t a2, uint32_t a3,
                                          uint32_t b0, uint32_t b1) {
    asm volatile(
        "mma.sync.aligned.m16n8k16.row.col.f16.f16.f16.f16 "
        "{%0,%1}, {%2,%3,%4,%5}, {%6,%7}, {%0,%1};"
        : "+r"(d[0]), "+r"(d[1])
        : "r"(a0), "r"(a1), "r"(a2), "r"(a3), "r"(b0), "r"(b1));
}

// ================= k_prep =================
// blocks 0..191: band rows of g_B
// blocks 192..287: bias
// blocks 288..291: coalesced transpose of wf halves into g_Ax / g_Ar
__global__ void k_prep(const float* __restrict__ wxs, const float* __restrict__ wxt,
    const float* __restrict__ wfs, const float* __restrict__ wft,
    const float* __restrict__ rws0, const float* __restrict__ rws1,
    const float* __restrict__ rws2, const float* __restrict__ rws3,
    const float* __restrict__ rwt0, const float* __restrict__ rwt1,
    const float* __restrict__ rwt2, const float* __restrict__ rwt3,
    const float* __restrict__ bxs,  const float* __restrict__ bxt,
    const float* __restrict__ bfs,  const float* __restrict__ bft,
    const float* __restrict__ rbs0, const float* __restrict__ rbs1,
    const float* __restrict__ rbs2, const float* __restrict__ rbs3,
    const float* __restrict__ rbt0, const float* __restrict__ rbt1,
    const float* __restrict__ rbt2, const float* __restrict__ rbt3) {
    int tid = threadIdx.x;
    if (blockIdx.x >= 288) {
        __shared__ float sm[96][97];
        int b2 = blockIdx.x - 288;
        int side = b2 >> 1, half = b2 & 1;
        const float* wf = side ? wft : wfs;
        float* dst = half ? g_Ar : g_Ax;
        for (int idx = tid; idx < 96 * 96; idx += blockDim.x) {
            int p = idx / 96, r = idx - p * 96;
            sm[p][r] = wf[p * 192 + half * 96 + r];
        }
        __syncthreads();
        for (int idx = tid; idx < 96 * 96; idx += blockDim.x) {
            int r = idx / 96, p = idx - r * 96;
            dst[(side * 96 + r) * 96 + p] = sm[p][r];
        }
        return;
    }
    if (blockIdx.x >= 192) {
        __shared__ float red[8];
        int p = blockIdx.x - 192;
        float c = 0.f;
        if (tid < 96) {
            int j = tid;
            c = wfs[p * 192 + j] * bxs[j] + wft[p * 192 + j] * bxt[j]
              + wfs[p * 192 + 96 + j] * (rbs0[j] + rbs1[j] + rbs2[j] + rbs3[j])
              + wft[p * 192 + 96 + j] * (rbt0[j] + rbt1[j] + rbt2[j] + rbt3[j]);
        }
        for (int o = 16; o; o >>= 1) c += __shfl_down_sync(0xffffffffu, c, o);
        if ((tid & 31) == 0) red[tid >> 5] = c;
        __syncthreads();
        if (tid == 0) {
            float s = bfs[p] + bft[p];
            #pragma unroll
            for (int i = 0; i < 4; ++i) s += red[i];
            g_bias[p] = s;
        }
        return;
    }
    __shared__ float r[512];
    __shared__ float red[8];
    __shared__ float s_su;
    int j = blockIdx.x;
    int side = j / 96, row = j % 96;
    const float* wx = side ? wxt : wxs;
    r[tid]       = wx[row * SEQ + tid];
    r[tid + 256] = wx[row * SEQ + tid + 256];
    __syncthreads();
    {
        float a = r[tid] + r[tid + 256];
        for (int o = 16; o; o >>= 1) a += __shfl_down_sync(0xffffffffu, a, o);
        if ((tid & 31) == 0) red[tid >> 5] = a;
        __syncthreads();
        if (tid == 0) {
            float s = 0.f;
            #pragma unroll
            for (int i = 0; i < 8; ++i) s += red[i];
            s_su = s;
        }
        __syncthreads();
    }
    float su = s_su;
    #pragma unroll
    for (int t = 0; t < 2; ++t) {
        int l = tid + t * 256;
        int lo = (l - 12 < 0) ? 0 : l - 12;
        int hi = (l + 12 > 511) ? 511 : l + 12;
        float band = 0.f;
        for (int m = lo; m <= hi; ++m) {
            float cnt = 1.f;
            if (l == 0)   cnt = (float)(13 - m);
            if (l == 511) cnt = (float)(m - 498);
            band += cnt * r[m];
        }
        band *= 0.04f;
        float v = side ? band : (r[l] - band);
        float ml = 0.f;
        if (l >= 499 && l <= 510) ml = 0.04f;
        if (l == 511)             ml = 0.52f;
        float coef = side ? (-ml) : (ml - (l == 511 ? 1.f : 0.f));
        v += su * coef;
        g_B[j * KTOT + l] = v;
    }
    if (tid < 96) {
        int q = tid;
        int i, g, dim, qq; qmap(q % 48, i, g, dim, qq);
        float rv = 0.f;
        if ((q / 48) == side) {
            const float* rw;
            if (!side) rw = (i == 0) ? rws0 : (i == 1) ? rws1 : (i == 2) ? rws2 : rws3;
            else       rw = (i == 0) ? rwt0 : (i == 1) ? rwt1 : (i == 2) ? rwt2 : rwt3;
            rv = rw[row * dim + qq];
        }
        g_B[j * KTOT + 512 + q] = rv;
    }
}

// ================= k_pgemm (validated fragment layout) =================
__global__ __launch_bounds__(128) void k_pgemm() {
    __shared__ float sA[32 * 96];
    __shared__ float sB[32][8];
    int tid = threadIdx.x;
    int tp = tid >> 2;
    int tc = tid & 3;
    int col0 = blockIdx.x * 8;
    const float* A = (col0 >= 512) ? g_Ar : g_Ax;
    float acc[3][2] = {};
    for (int jc = 0; jc < 6; ++jc) {
        __syncthreads();
        const float4* srcA = reinterpret_cast<const float4*>(A + jc * 32 * 96);
        #pragma unroll
        for (int i = 0; i < 6; ++i)
            reinterpret_cast<float4*>(sA)[tid + i * 128] = srcA[tid + i * 128];
        #pragma unroll
        for (int i = 0; i < 2; ++i) {
            int idx = tid + i * 128;
            int jj = idx >> 3, cc = idx & 7;
            sB[jj][cc] = g_B[(jc * 32 + jj) * KTOT + col0 + cc];
        }
        __syncthreads();
        #pragma unroll 8
        for (int jj = 0; jj < 32; ++jj) {
            float b0 = sB[jj][tc * 2], b1 = sB[jj][tc * 2 + 1];
            #pragma unroll
            for (int u = 0; u < 3; ++u) {
                float a = sA[jj * 96 + tp * 3 + u];
                acc[u][0] += a * b0;
                acc[u][1] += a * b1;
            }
        }
    }
    #pragma unroll
    for (int v = 0; v < 2; ++v) {
        int col = col0 + tc * 2 + v;
        float add = (col == 511) ? 1.f : 0.f;
        #pragma unroll
        for (int u = 0; u < 3; ++u) {
            float val = acc[u][v] + add;
            int p = tp * 3 + u;
            __half hv = __float2half(val);
            int lane = (p & 7) * 4 + ((col & 7) >> 1);
            int reg  = (col >> 3) & 1;
            long off = ((((long)(col >> 5) * 2 + ((col >> 4) & 1)) * 12 + (p >> 3)) * 32
                        + lane) * 8 + reg * 4 + (col & 1) * 2;
            *(uint16_t*)((char*)g_Bf + off) = __half_as_ushort(hv);
        }
    }
}

// ================= k_main: fp16-accum HMMA + segmented fp32 promotion =================
// R10 structure (validated fastest); only the accumulate path changes.
__global__ __launch_bounds__(256, 3) void k_main(
    const float* __restrict__ x, const float* __restrict__ rds,
    const float* __restrict__ rdt, const int* __restrict__ index,
    float* __restrict__ out) {
    __shared__ int sxb[64], sdb[64], sob[64];
    __shared__ const float* qptr[96];
    __shared__ float sbias[96];
    extern __shared__ char dsm_raw[];

    int tid = threadIdx.x;
    int wid = tid >> 5, lane = tid & 31;
    int j0 = blockIdx.x * 64;

    if (tid < 64) {
        int jj = j0 + tid;
        int b = jj / NCH, c = jj - b * NCH;
        sxb[tid] = b * SEQ * NCH + c;
        sob[tid] = b * PRED * NCH + c;
        sdb[tid] = index[b] * PRED * NCH + c;
    }
    if (tid < 96) {
        int q = tid;
        int i, g, dim, qq; qmap(q % 48, i, g, dim, qq);
        const float* base = (q < 48) ? rds : rdt;
        qptr[q] = base + (size_t)i * (NDICT * PRED * NCH) + (size_t)qq * g * NCH;
        sbias[tid] = g_bias[tid];
    }
    __syncthreads();

    uint32_t db = (uint32_t)__cvta_generic_to_shared(dsm_raw);
    uint32_t ab = (db + 127u) & ~127u;
    uint32_t AF[3] = { ab, ab + 5120, ab + 10240 };           // 64 rows x 80B
    uint32_t BF[4] = { ab + 15360, ab + 21504, ab + 27648, ab + 33792 };

    int m  = tid & 63;           // producer column
    int kh = tid >> 6;           // 0..3: k-octet of chunk
    const float* xcol = x + sxb[m];
    int dcol = sdb[m];
    uint32_t arow_off = (uint32_t)(m * 80 + kh * 16);

    int mw = wid & 3;            // m-tile (16 rows)
    int ng = wid >> 2;           // n-group: nt 6*ng .. 6*ng+5
    uint32_t aoff = (uint32_t)((mw * 16 + (lane & 7) + ((lane >> 3) & 1) * 8) * 80
                               + ((lane >> 4) & 1) * 16);
    uint32_t boff = (uint32_t)(ng * 6 * 256 + lane * 8);

    float facc[6][4];            // fp32 master accumulators
    uint32_t hacc[6][2];         // fp16 segment accumulators
    #pragma unroll
    for (int nt = 0; nt < 6; ++nt) {
        #pragma unroll
        for (int v = 0; v < 4; ++v) facc[nt][v] = 0.f;
        hacc[nt][0] = 0u; hacc[nt][1] = 0u;
    }

    float v[8];

    #define LDGA(cc) do {                                                    \
        int _k0 = (cc) * KC + kh * 8;                                        \
        if (_k0 < 512) {                                                     \
            const float* _s = xcol + (size_t)_k0 * NCH;                      \
            _Pragma("unroll")                                                \
            for (int i_ = 0; i_ < 8; ++i_) v[i_] = _s[i_ * NCH];             \
        } else {                                                             \
            int _q0 = _k0 - 512;                                             \
            _Pragma("unroll")                                                \
            for (int i_ = 0; i_ < 8; ++i_) v[i_] = qptr[_q0 + i_][dcol];     \
        }                                                                    \
    } while (0)

    #define STSA(abuf) do {                                                  \
        uint32_t h_[4];                                                      \
        _Pragma("unroll")                                                    \
        for (int t_ = 0; t_ < 4; ++t_)                                       \
            h_[t_] = pack_f16x2(v[2 * t_], v[2 * t_ + 1]);                   \
        sts128(AF[abuf] + arow_off, h_[0], h_[1], h_[2], h_[3]);             \
    } while (0)

    #define FILLB(bbuf, cc) do {                                             \
        const char* _sf = (const char*)g_Bf + (size_t)(cc) * 6144;           \
        if (tid < 192) {                                                     \
            uint32_t off = (uint32_t)tid * 16u;                              \
            cpa16(BF[bbuf] + off, _sf + off);                                \
            cpa16(BF[bbuf] + off + 3072, _sf + off + 3072);                  \
        }                                                                    \
    } while (0)

    // prologue: A chunk 0 staged, v holds chunk 1; B chunks 0,1 committed.
    LDGA(0); STSA(0);
    LDGA(1);
    FILLB(0, 0); cp_commit();
    FILLB(1, 1); cp_commit();

    #pragma unroll 1
    for (int c = 0; c < NCHUNK; ++c) {
        int ac = c % 3;                    // A buffer holding chunk c
        int bc = c & 3;                    // B buffer holding chunk c
        if (c + 1 < NCHUNK) STSA((c + 1) % 3);      // v -> A[c+1]
        if (c + 2 < NCHUNK) {
            LDGA(c + 2);                            // regs for next STSA
            FILLB((c + 2) & 3, c + 2);
        }
        cp_commit();                                // uniform group count
        cp_wait2();                                 // B(c) arrived
        __syncthreads();                            // A(c+1)/B visible

        #pragma unroll
        for (int kt = 0; kt < 2; ++kt) {
            uint32_t a0, a1, a2, a3;
            ldmat4(a0, a1, a2, a3, AF[ac] + aoff + kt * 32);
            uint32_t bb = BF[bc] + (uint32_t)(kt * 3072) + boff;
            #pragma unroll
            for (int nt = 0; nt < 6; ++nt) {
                uint32_t b0, b1;
                lds64(b0, b1, bb + nt * 256);
                mma16816h(hacc[nt], a0, a1, a2, a3, b0, b1);
            }
        }

        // segment promotion: keep fp16 accumulation windows short (5,5,5,4 chunks)
        if (c == 4 || c == 9 || c == 14 || c == 18) {
            #pragma unroll
            for (int nt = 0; nt < 6; ++nt) {
                float2 f0 = __half22float2(*reinterpret_cast<__half2*>(&hacc[nt][0]));
                float2 f1 = __half22float2(*reinterpret_cast<__half2*>(&hacc[nt][1]));
                facc[nt][0] += f0.x; facc[nt][1] += f0.y;
                facc[nt][2] += f1.x; facc[nt][3] += f1.y;
                hacc[nt][0] = 0u; hacc[nt][1] = 0u;
            }
        }
    }
    #undef LDGA
    #undef STSA
    #undef FILLB

    // ---- epilogue ----
    int g = lane >> 2, tg = lane & 3;
    int r0 = mw * 16 + g, r1 = r0 + 8;
    int ob0 = sob[r0], ob1 = sob[r1];
    #pragma unroll
    for (int nt = 0; nt < 6; ++nt) {
        int p0 = (ng * 6 + nt) * 8 + tg * 2;
        float sb0 = sbias[p0], sb1 = sbias[p0 + 1];
        out[ob0 + p0 * NCH]       = facc[nt][0] + sb0;
        out[ob0 + (p0 + 1) * NCH] = facc[nt][1] + sb1;
        out[ob1 + p0 * NCH]       = facc[nt][2] + sb0;
        out[ob1 + (p0 + 1) * NCH] = facc[nt][3] + sb1;
    }
}

// ---------------- launch ----------------
#define DSM_BYTES (39936 + 256)

extern "C" void kernel_launch(void* const* d_in, const int* in_sizes, int n_in,
                              void* d_out, int out_size) {
    const float* x   = (const float*)d_in[0];
    const int*   idx = (const int*)d_in[1];
    const float* rds = (const float*)d_in[2];
    const float* rdt = (const float*)d_in[3];
    const float* wxs = (const float*)d_in[4];
    const float* bxs = (const float*)d_in[5];
    const float* wxt = (const float*)d_in[6];
    const float* bxt = (const float*)d_in[7];

    const float *wfs, *bfs, *wft, *bft;
    const float *rws[4], *rbs[4], *rwt[4], *rbt[4];

    if (in_sizes[8] == PRED * 2 * PRED) {
        wfs = (const float*)d_in[8];  bfs = (const float*)d_in[9];
        wft = (const float*)d_in[10]; bft = (const float*)d_in[11];
        for (int i = 0; i < 4; ++i) {
            rws[i] = (const float*)d_in[12 + 4 * i];
            rbs[i] = (const float*)d_in[13 + 4 * i];
            rwt[i] = (const float*)d_in[14 + 4 * i];
            rbt[i] = (const float*)d_in[15 + 4 * i];
        }
    } else {
        for (int i = 0; i < 4; ++i) {
            rws[i] = (const float*)d_in[8 + i];
            rbs[i] = (const float*)d_in[12 + i];
            rwt[i] = (const float*)d_in[16 + i];
            rbt[i] = (const float*)d_in[20 + i];
        }
        wfs = (const float*)d_in[24]; bfs = (const float*)d_in[25];
        wft = (const float*)d_in[26]; bft = (const float*)d_in[27];
    }

    float* out = (float*)d_out;

    cudaFuncSetAttribute(k_main, cudaFuncAttributeMaxDynamicSharedMemorySize,
                         DSM_BYTES);

    k_prep<<<292, 256>>>(wxs, wxt, wfs, wft,
                         rws[0], rws[1], rws[2], rws[3],
                         rwt[0], rwt[1], rwt[2], rwt[3],
                         bxs, bxt, bfs, bft,
                         rbs[0], rbs[1], rbs[2], rbs[3],
                         rbt[0], rbt[1], rbt[2], rbt[3]);
    k_pgemm<<<76, 128>>>();
    k_main<<<NTILES, 256, DSM_BYTES>>>(x, rds, rdt, idx, out);
}

// round 13
// speedup vs baseline: 1.2135x; 1.0057x over previous
#include <cuda_runtime.h>
#include <cuda_bf16.h>
#include <cuda_fp16.h>
#include <cstdint>

#define PRED  96
#define SEQ   512
#define NCH   321
#define NB    64
#define KTOT  608
#define NDICT 2000
#define NCOL  20544
#define KC    32
#define NCHUNK 19          // 608 / 32 exact
#define COLS  192
#define NTILES 107         // 20544 / 192 exact -> one wave, <=1 CTA/SM

// ---------------- device scratch ----------------
__device__ float g_bias[PRED];
__device__ float g_B[192 * KTOT];       // [j][col]
__device__ float g_Ax[192 * PRED];      // [j][p]
__device__ float g_Ar[192 * PRED];      // [j][p]
// W in mma-fragment layout, fp16: [chunk19][kt2][nt12][lane32][reg2] pairs
__device__ uint16_t g_Bf[NCHUNK * 3072];

__device__ __forceinline__ void qmap(int q, int &i, int &g, int &dim, int &qq) {
    if (q < 24)      { i = 0; g = 4;  dim = 24; qq = q;      }
    else if (q < 36) { i = 1; g = 8;  dim = 12; qq = q - 24; }
    else if (q < 44) { i = 2; g = 12; dim = 8;  qq = q - 36; }
    else             { i = 3; g = 24; dim = 4;  qq = q - 44; }
}

// ---------------- asm helpers ----------------
__device__ __forceinline__ uint32_t pack_f16x2(float lo, float hi) {
    uint32_t r;
    asm("cvt.rn.f16x2.f32 %0, %1, %2;" : "=r"(r) : "f"(hi), "f"(lo));
    return r;
}
__device__ __forceinline__ void sts128(uint32_t a, uint32_t v0, uint32_t v1,
                                       uint32_t v2, uint32_t v3) {
    asm volatile("st.shared.v4.b32 [%0], {%1,%2,%3,%4};"
                 :: "r"(a), "r"(v0), "r"(v1), "r"(v2), "r"(v3));
}
__device__ __forceinline__ void cpa16(uint32_t d, const void* s) {
    asm volatile("cp.async.cg.shared.global [%0], [%1], 16;" :: "r"(d), "l"(s));
}
__device__ __forceinline__ void cp_commit() { asm volatile("cp.async.commit_group;"); }
__device__ __forceinline__ void cp_wait2()  { asm volatile("cp.async.wait_group 2;" ::: "memory"); }

__device__ __forceinline__ void ldmat4(uint32_t* a, uint32_t addr) {
    asm volatile("ldmatrix.sync.aligned.m8n8.x4.shared.b16 {%0,%1,%2,%3}, [%4];"
                 : "=r"(a[0]), "=r"(a[1]), "=r"(a[2]), "=r"(a[3]) : "r"(addr));
}
__device__ __forceinline__ void lds64(uint32_t &b0, uint32_t &b1, uint32_t addr) {
    asm volatile("ld.shared.v2.b32 {%0,%1}, [%2];" : "=r"(b0), "=r"(b1) : "r"(addr));
}
// fp16-accumulate HMMA (full-rate)
__device__ __forceinline__ void mma16816h(uint32_t* d, const uint32_t* a,
                                          uint32_t b0, uint32_t b1) {
    asm volatile(
        "mma.sync.aligned.m16n8k16.row.col.f16.f16.f16.f16 "
        "{%0,%1}, {%2,%3,%4,%5}, {%6,%7}, {%0,%1};"
        : "+r"(d[0]), "+r"(d[1])
        : "r"(a[0]), "r"(a[1]), "r"(a[2]), "r"(a[3]), "r"(b0), "r"(b1));
}

// ================= k_prep (validated) =================
__global__ void k_prep(const float* __restrict__ wxs, const float* __restrict__ wxt,
    const float* __restrict__ wfs, const float* __restrict__ wft,
    const float* __restrict__ rws0, const float* __restrict__ rws1,
    const float* __restrict__ rws2, const float* __restrict__ rws3,
    const float* __restrict__ rwt0, const float* __restrict__ rwt1,
    const float* __restrict__ rwt2, const float* __restrict__ rwt3,
    const float* __restrict__ bxs,  const float* __restrict__ bxt,
    const float* __restrict__ bfs,  const float* __restrict__ bft,
    const float* __restrict__ rbs0, const float* __restrict__ rbs1,
    const float* __restrict__ rbs2, const float* __restrict__ rbs3,
    const float* __restrict__ rbt0, const float* __restrict__ rbt1,
    const float* __restrict__ rbt2, const float* __restrict__ rbt3) {
    int tid = threadIdx.x;
    if (blockIdx.x >= 288) {
        __shared__ float sm[96][97];
        int b2 = blockIdx.x - 288;
        int side = b2 >> 1, half = b2 & 1;
        const float* wf = side ? wft : wfs;
        float* dst = half ? g_Ar : g_Ax;
        for (int idx = tid; idx < 96 * 96; idx += blockDim.x) {
            int p = idx / 96, r = idx - p * 96;
            sm[p][r] = wf[p * 192 + half * 96 + r];
        }
        __syncthreads();
        for (int idx = tid; idx < 96 * 96; idx += blockDim.x) {
            int r = idx / 96, p = idx - r * 96;
            dst[(side * 96 + r) * 96 + p] = sm[p][r];
        }
        return;
    }
    if (blockIdx.x >= 192) {
        __shared__ float red[8];
        int p = blockIdx.x - 192;
        float c = 0.f;
        if (tid < 96) {
            int j = tid;
            c = wfs[p * 192 + j] * bxs[j] + wft[p * 192 + j] * bxt[j]
              + wfs[p * 192 + 96 + j] * (rbs0[j] + rbs1[j] + rbs2[j] + rbs3[j])
              + wft[p * 192 + 96 + j] * (rbt0[j] + rbt1[j] + rbt2[j] + rbt3[j]);
        }
        for (int o = 16; o; o >>= 1) c += __shfl_down_sync(0xffffffffu, c, o);
        if ((tid & 31) == 0) red[tid >> 5] = c;
        __syncthreads();
        if (tid == 0) {
            float s = bfs[p] + bft[p];
            #pragma unroll
            for (int i = 0; i < 4; ++i) s += red[i];
            g_bias[p] = s;
        }
        return;
    }
    __shared__ float r[512];
    __shared__ float red[8];
    __shared__ float s_su;
    int j = blockIdx.x;
    int side = j / 96, row = j % 96;
    const float* wx = side ? wxt : wxs;
    r[tid]       = wx[row * SEQ + tid];
    r[tid + 256] = wx[row * SEQ + tid + 256];
    __syncthreads();
    {
        float a = r[tid] + r[tid + 256];
        for (int o = 16; o; o >>= 1) a += __shfl_down_sync(0xffffffffu, a, o);
        if ((tid & 31) == 0) red[tid >> 5] = a;
        __syncthreads();
        if (tid == 0) {
            float s = 0.f;
            #pragma unroll
            for (int i = 0; i < 8; ++i) s += red[i];
            s_su = s;
        }
        __syncthreads();
    }
    float su = s_su;
    #pragma unroll
    for (int t = 0; t < 2; ++t) {
        int l = tid + t * 256;
        int lo = (l - 12 < 0) ? 0 : l - 12;
        int hi = (l + 12 > 511) ? 511 : l + 12;
        float band = 0.f;
        for (int m = lo; m <= hi; ++m) {
            float cnt = 1.f;
            if (l == 0)   cnt = (float)(13 - m);
            if (l == 511) cnt = (float)(m - 498);
            band += cnt * r[m];
        }
        band *= 0.04f;
        float v = side ? band : (r[l] - band);
        float ml = 0.f;
        if (l >= 499 && l <= 510) ml = 0.04f;
        if (l == 511)             ml = 0.52f;
        float coef = side ? (-ml) : (ml - (l == 511 ? 1.f : 0.f));
        v += su * coef;
        g_B[j * KTOT + l] = v;
    }
    if (tid < 96) {
        int q = tid;
        int i, g, dim, qq; qmap(q % 48, i, g, dim, qq);
        float rv = 0.f;
        if ((q / 48) == side) {
            const float* rw;
            if (!side) rw = (i == 0) ? rws0 : (i == 1) ? rws1 : (i == 2) ? rws2 : rws3;
            else       rw = (i == 0) ? rwt0 : (i == 1) ? rwt1 : (i == 2) ? rwt2 : rwt3;
            rv = rw[row * dim + qq];
        }
        g_B[j * KTOT + 512 + q] = rv;
    }
}

// ================= k_pgemm (validated fragment layout) =================
__global__ __launch_bounds__(128) void k_pgemm() {
    __shared__ float sA[32 * 96];
    __shared__ float sB[32][8];
    int tid = threadIdx.x;
    int tp = tid >> 2;
    int tc = tid & 3;
    int col0 = blockIdx.x * 8;
    const float* A = (col0 >= 512) ? g_Ar : g_Ax;
    float acc[3][2] = {};
    for (int jc = 0; jc < 6; ++jc) {
        __syncthreads();
        const float4* srcA = reinterpret_cast<const float4*>(A + jc * 32 * 96);
        #pragma unroll
        for (int i = 0; i < 6; ++i)
            reinterpret_cast<float4*>(sA)[tid + i * 128] = srcA[tid + i * 128];
        #pragma unroll
        for (int i = 0; i < 2; ++i) {
            int idx = tid + i * 128;
            int jj = idx >> 3, cc = idx & 7;
            sB[jj][cc] = g_B[(jc * 32 + jj) * KTOT + col0 + cc];
        }
        __syncthreads();
        #pragma unroll 8
        for (int jj = 0; jj < 32; ++jj) {
            float b0 = sB[jj][tc * 2], b1 = sB[jj][tc * 2 + 1];
            #pragma unroll
            for (int u = 0; u < 3; ++u) {
                float a = sA[jj * 96 + tp * 3 + u];
                acc[u][0] += a * b0;
                acc[u][1] += a * b1;
            }
        }
    }
    #pragma unroll
    for (int v = 0; v < 2; ++v) {
        int col = col0 + tc * 2 + v;
        float add = (col == 511) ? 1.f : 0.f;
        #pragma unroll
        for (int u = 0; u < 3; ++u) {
            float val = acc[u][v] + add;
            int p = tp * 3 + u;
            __half hv = __float2half(val);
            int lane = (p & 7) * 4 + ((col & 7) >> 1);
            int reg  = (col >> 3) & 1;
            long off = ((((long)(col >> 5) * 2 + ((col >> 4) & 1)) * 12 + (p >> 3)) * 32
                        + lane) * 8 + reg * 4 + (col & 1) * 2;
            *(uint16_t*)((char*)g_Bf + off) = __half_as_ushort(hv);
        }
    }
}

// ================= k_main: 192-col tiles, 1 CTA/SM, 12 warps (4mw x 3ng) =================
__global__ __launch_bounds__(384, 1) void k_main(
    const float* __restrict__ x, const float* __restrict__ rds,
    const float* __restrict__ rdt, const int* __restrict__ index,
    float* __restrict__ out) {
    __shared__ int sxb[COLS], sdb[COLS], sob[COLS];
    __shared__ const float* qptr[96];
    __shared__ float sbias[96];
    extern __shared__ char dsm_raw[];

    int tid = threadIdx.x;
    int wid = tid >> 5, lane = tid & 31;
    int j0 = blockIdx.x * COLS;

    if (tid < COLS) {
        int jj = j0 + tid;
        int b = jj / NCH, c = jj - b * NCH;
        sxb[tid] = b * SEQ * NCH + c;
        sob[tid] = b * PRED * NCH + c;
        sdb[tid] = index[b] * PRED * NCH + c;
    }
    if (tid < 96) {
        int q = tid;
        int i, g, dim, qq; qmap(q % 48, i, g, dim, qq);
        const float* base = (q < 48) ? rds : rdt;
        qptr[q] = base + (size_t)i * (NDICT * PRED * NCH) + (size_t)qq * g * NCH;
        sbias[tid] = g_bias[tid];
    }
    __syncthreads();

    uint32_t db = (uint32_t)__cvta_generic_to_shared(dsm_raw);
    uint32_t ab = (db + 127u) & ~127u;
    // A: 192 rows x 80B = 15360 per buffer, 3 buffers; B: 6144 x 4 buffers
    uint32_t AF[3] = { ab, ab + 15360, ab + 30720 };
    uint32_t BF[4] = { ab + 46080, ab + 52224, ab + 58368, ab + 64512 };

    int m  = tid % COLS;         // producer column
    int kh = tid / COLS;         // 0/1: k-half of chunk (16 k each)
    const float* xcol = x + sxb[m];
    int dcol = sdb[m];
    uint32_t arow_off = (uint32_t)(m * 80 + kh * 32);

    int mw = wid & 3;            // m-group: rows mw*48 .. mw*48+47 (3 mtiles)
    int ng = wid >> 2;           // n-group: nt ng*4 .. ng*4+3
    uint32_t aoff[3];
    #pragma unroll
    for (int s = 0; s < 3; ++s)
        aoff[s] = (uint32_t)((mw * 48 + s * 16 + (lane & 7) + ((lane >> 3) & 1) * 8) * 80
                             + ((lane >> 4) & 1) * 16);
    uint32_t boff = (uint32_t)(ng * 4 * 256 + lane * 8);

    float facc[3][4][4];         // fp32 master accumulators [s][n][v]
    uint32_t hacc[3][4][2];      // fp16 segment accumulators
    #pragma unroll
    for (int s = 0; s < 3; ++s)
        #pragma unroll
        for (int n = 0; n < 4; ++n) {
            #pragma unroll
            for (int v = 0; v < 4; ++v) facc[s][n][v] = 0.f;
            hacc[s][n][0] = 0u; hacc[s][n][1] = 0u;
        }

    float v[16];

    #define LDGA(cc) do {                                                    \
        int _k0 = (cc) * KC + kh * 16;                                       \
        if (_k0 < 512) {                                                     \
            const float* _s = xcol + (size_t)_k0 * NCH;                      \
            _Pragma("unroll")                                                \
            for (int i_ = 0; i_ < 16; ++i_) v[i_] = _s[i_ * NCH];            \
        } else {                                                             \
            int _q0 = _k0 - 512;                                             \
            _Pragma("unroll")                                                \
            for (int i_ = 0; i_ < 16; ++i_) v[i_] = qptr[_q0 + i_][dcol];    \
        }                                                                    \
    } while (0)

    #define STSA(abuf) do {                                                  \
        uint32_t h_[8];                                                      \
        _Pragma("unroll")                                                    \
        for (int t_ = 0; t_ < 8; ++t_)                                       \
            h_[t_] = pack_f16x2(v[2 * t_], v[2 * t_ + 1]);                   \
        sts128(AF[abuf] + arow_off,      h_[0], h_[1], h_[2], h_[3]);        \
        sts128(AF[abuf] + arow_off + 16, h_[4], h_[5], h_[6], h_[7]);        \
    } while (0)

    #define FILLB(bbuf, cc) do {                                             \
        const char* _sf = (const char*)g_Bf + (size_t)(cc) * 6144;           \
        uint32_t off = (uint32_t)tid * 16u;                                  \
        cpa16(BF[bbuf] + off, _sf + off);                                    \
    } while (0)

    // prologue: A chunk 0 staged, v holds chunk 1; B chunks 0,1 committed.
    LDGA(0); STSA(0);
    LDGA(1);
    FILLB(0, 0); cp_commit();
    FILLB(1, 1); cp_commit();

    #pragma unroll 1
    for (int c = 0; c < NCHUNK; ++c) {
        int ac = c % 3;                    // A buffer holding chunk c
        int bc = c & 3;                    // B buffer holding chunk c
        if (c + 1 < NCHUNK) STSA((c + 1) % 3);      // v -> A[c+1]
        if (c + 2 < NCHUNK) {
            LDGA(c + 2);                            // regs for next STSA
            FILLB((c + 2) & 3, c + 2);
        }
        cp_commit();                                // uniform group count
        cp_wait2();                                 // B(c) arrived
        __syncthreads();                            // A(c+1)/B visible

        #pragma unroll
        for (int kt = 0; kt < 2; ++kt) {
            uint32_t a[3][4];
            #pragma unroll
            for (int s = 0; s < 3; ++s)
                ldmat4(a[s], AF[ac] + aoff[s] + kt * 32);
            uint32_t bb = BF[bc] + (uint32_t)(kt * 3072) + boff;
            #pragma unroll
            for (int n = 0; n < 4; ++n) {
                uint32_t b0, b1;
                lds64(b0, b1, bb + n * 256);
                #pragma unroll
                for (int s = 0; s < 3; ++s)
                    mma16816h(hacc[s][n], a[s], b0, b1);
            }
        }

        // segment promotion: fp16 accumulation windows of 5,5,5,4 chunks
        if (c == 4 || c == 9 || c == 14 || c == 18) {
            #pragma unroll
            for (int s = 0; s < 3; ++s)
                #pragma unroll
                for (int n = 0; n < 4; ++n) {
                    float2 f0 = __half22float2(*reinterpret_cast<__half2*>(&hacc[s][n][0]));
                    float2 f1 = __half22float2(*reinterpret_cast<__half2*>(&hacc[s][n][1]));
                    facc[s][n][0] += f0.x; facc[s][n][1] += f0.y;
                    facc[s][n][2] += f1.x; facc[s][n][3] += f1.y;
                    hacc[s][n][0] = 0u; hacc[s][n][1] = 0u;
                }
        }
    }
    #undef LDGA
    #undef STSA
    #undef FILLB

    // ---- epilogue ----
    int g = lane >> 2, tg = lane & 3;
    #pragma unroll
    for (int s = 0; s < 3; ++s) {
        int r0 = mw * 48 + s * 16 + g, r1 = r0 + 8;
        int ob0 = sob[r0], ob1 = sob[r1];
        #pragma unroll
        for (int n = 0; n < 4; ++n) {
            int p0 = (ng * 4 + n) * 8 + tg * 2;
            float sb0 = sbias[p0], sb1 = sbias[p0 + 1];
            out[ob0 + p0 * NCH]       = facc[s][n][0] + sb0;
            out[ob0 + (p0 + 1) * NCH] = facc[s][n][1] + sb1;
            out[ob1 + p0 * NCH]       = facc[s][n][2] + sb0;
            out[ob1 + (p0 + 1) * NCH] = facc[s][n][3] + sb1;
        }
    }
}

// ---------------- launch ----------------
#define DSM_BYTES (70656 + 256)

extern "C" void kernel_launch(void* const* d_in, const int* in_sizes, int n_in,
                              void* d_out, int out_size) {
    const float* x   = (const float*)d_in[0];
    const int*   idx = (const int*)d_in[1];
    const float* rds = (const float*)d_in[2];
    const float* rdt = (const float*)d_in[3];
    const float* wxs = (const float*)d_in[4];
    const float* bxs = (const float*)d_in[5];
    const float* wxt = (const float*)d_in[6];
    const float* bxt = (const float*)d_in[7];

    const float *wfs, *bfs, *wft, *bft;
    const float *rws[4], *rbs[4], *rwt[4], *rbt[4];

    if (in_sizes[8] == PRED * 2 * PRED) {
        wfs = (const float*)d_in[8];  bfs = (const float*)d_in[9];
        wft = (const float*)d_in[10]; bft = (const float*)d_in[11];
        for (int i = 0; i < 4; ++i) {
            rws[i] = (const float*)d_in[12 + 4 * i];
            rbs[i] = (const float*)d_in[13 + 4 * i];
            rwt[i] = (const float*)d_in[14 + 4 * i];
            rbt[i] = (const float*)d_in[15 + 4 * i];
        }
    } else {
        for (int i = 0; i < 4; ++i) {
            rws[i] = (const float*)d_in[8 + i];
            rbs[i] = (const float*)d_in[12 + i];
            rwt[i] = (const float*)d_in[16 + i];
            rbt[i] = (const float*)d_in[20 + i];
        }
        wfs = (const float*)d_in[24]; bfs = (const float*)d_in[25];
        wft = (const float*)d_in[26]; bft = (const float*)d_in[27];
    }

    float* out = (float*)d_out;

    cudaFuncSetAttribute(k_main, cudaFuncAttributeMaxDynamicSharedMemorySize,
                         DSM_BYTES);

    k_prep<<<292, 256>>>(wxs, wxt, wfs, wft,
                         rws[0], rws[1], rws[2], rws[3],
                         rwt[0], rwt[1], rwt[2], rwt[3],
                         bxs, bxt, bfs, bft,
                         rbs[0], rbs[1], rbs[2], rbs[3],
                         rbt[0], rbt[1], rbt[2], rbt[3]);
    k_pgemm<<<76, 128>>>();
    k_main<<<NTILES, 384, DSM_BYTES>>>(x, rds, rdt, idx, out);
}

// round 14
// speedup vs baseline: 1.3456x; 1.1089x over previous
#include <cuda_runtime.h>
#include <cuda_fp16.h>
#include <cstdint>

#define PRED  96
#define SEQ   512
#define NCH   321
#define NB    64
#define KTOT  608
#define NDICT 2000
#define NCOL  20544
#define KC    64
#define NCHUNK 10          // 9 x 64k + 1 x 32k
#define COLS  192
#define NTILES 107         // 20544 / 192 exact -> one wave, <=1 CTA/SM

// ---------------- device scratch ----------------
__device__ float g_bias[PRED];
__device__ float g_B[192 * KTOT];       // [j][col]
__device__ float g_Ax[192 * PRED];      // [j][p]
__device__ float g_Ar[192 * PRED];      // [j][p]
// W in mma-fragment layout, fp16: [k32grp19][kt2][nt12][lane32][reg2] pairs
__device__ uint16_t g_Bf[19 * 3072];

__device__ __forceinline__ void qmap(int q, int &i, int &g, int &dim, int &qq) {
    if (q < 24)      { i = 0; g = 4;  dim = 24; qq = q;      }
    else if (q < 36) { i = 1; g = 8;  dim = 12; qq = q - 24; }
    else if (q < 44) { i = 2; g = 12; dim = 8;  qq = q - 36; }
    else             { i = 3; g = 24; dim = 4;  qq = q - 44; }
}

// ---------------- asm helpers ----------------
__device__ __forceinline__ uint32_t pack_f16x2(float lo, float hi) {
    uint32_t r;
    asm("cvt.rn.f16x2.f32 %0, %1, %2;" : "=r"(r) : "f"(hi), "f"(lo));
    return r;
}
__device__ __forceinline__ void sts128(uint32_t a, uint32_t v0, uint32_t v1,
                                       uint32_t v2, uint32_t v3) {
    asm volatile("st.shared.v4.b32 [%0], {%1,%2,%3,%4};"
                 :: "r"(a), "r"(v0), "r"(v1), "r"(v2), "r"(v3));
}
__device__ __forceinline__ void cpa16(uint32_t d, const void* s) {
    asm volatile("cp.async.cg.shared.global [%0], [%1], 16;" :: "r"(d), "l"(s));
}
__device__ __forceinline__ void cp_commit() { asm volatile("cp.async.commit_group;"); }
__device__ __forceinline__ void cp_wait2()  { asm volatile("cp.async.wait_group 2;" ::: "memory"); }

__device__ __forceinline__ void ldmat4(uint32_t* a, uint32_t addr) {
    asm volatile("ldmatrix.sync.aligned.m8n8.x4.shared.b16 {%0,%1,%2,%3}, [%4];"
                 : "=r"(a[0]), "=r"(a[1]), "=r"(a[2]), "=r"(a[3]) : "r"(addr));
}
__device__ __forceinline__ void lds64(uint32_t &b0, uint32_t &b1, uint32_t addr) {
    asm volatile("ld.shared.v2.b32 {%0,%1}, [%2];" : "=r"(b0), "=r"(b1) : "r"(addr));
}
__device__ __forceinline__ void mma16816(float* d, const uint32_t* a,
                                         uint32_t b0, uint32_t b1) {
    asm volatile(
        "mma.sync.aligned.m16n8k16.row.col.f32.f16.f16.f32 "
        "{%0,%1,%2,%3}, {%4,%5,%6,%7}, {%8,%9}, {%0,%1,%2,%3};"
        : "+f"(d[0]), "+f"(d[1]), "+f"(d[2]), "+f"(d[3])
        : "r"(a[0]), "r"(a[1]), "r"(a[2]), "r"(a[3]), "r"(b0), "r"(b1));
}

// ================= k_prep: 100 blocks, one wave =================
// blocks 0..95: band rows of g_B for BOTH sides + bias[j]
// blocks 96..99: coalesced transpose of wf halves into g_Ax / g_Ar
__global__ void k_prep(const float* __restrict__ wxs, const float* __restrict__ wxt,
    const float* __restrict__ wfs, const float* __restrict__ wft,
    const float* __restrict__ rws0, const float* __restrict__ rws1,
    const float* __restrict__ rws2, const float* __restrict__ rws3,
    const float* __restrict__ rwt0, const float* __restrict__ rwt1,
    const float* __restrict__ rwt2, const float* __restrict__ rwt3,
    const float* __restrict__ bxs,  const float* __restrict__ bxt,
    const float* __restrict__ bfs,  const float* __restrict__ bft,
    const float* __restrict__ rbs0, const float* __restrict__ rbs1,
    const float* __restrict__ rbs2, const float* __restrict__ rbs3,
    const float* __restrict__ rbt0, const float* __restrict__ rbt1,
    const float* __restrict__ rbt2, const float* __restrict__ rbt3) {
    int tid = threadIdx.x;
    if (blockIdx.x >= 96) {
        __shared__ float sm[96][97];
        int b2 = blockIdx.x - 96;
        int side = b2 >> 1, half = b2 & 1;
        const float* wf = side ? wft : wfs;
        float* dst = half ? g_Ar : g_Ax;
        for (int idx = tid; idx < 96 * 96; idx += blockDim.x) {
            int p = idx / 96, r = idx - p * 96;
            sm[p][r] = wf[p * 192 + half * 96 + r];
        }
        __syncthreads();
        for (int idx = tid; idx < 96 * 96; idx += blockDim.x) {
            int r = idx / 96, p = idx - r * 96;
            dst[(side * 96 + r) * 96 + p] = sm[p][r];
        }
        return;
    }
    __shared__ float rs[512], rt[512];
    __shared__ float red1[16], red2[16], redb[16];
    __shared__ float s_sus, s_sut;
    int j = blockIdx.x;
    rs[tid] = wxs[j * SEQ + tid];
    rt[tid] = wxt[j * SEQ + tid];

    // bias partial (threads 0..191)
    float bc = 0.f;
    if (tid < 96) {
        bc = wfs[j * 192 + tid] * bxs[tid] + wft[j * 192 + tid] * bxt[tid];
    } else if (tid < 192) {
        int t2 = tid - 96;
        bc = wfs[j * 192 + 96 + t2] * (rbs0[t2] + rbs1[t2] + rbs2[t2] + rbs3[t2])
           + wft[j * 192 + 96 + t2] * (rbt0[t2] + rbt1[t2] + rbt2[t2] + rbt3[t2]);
    }
    __syncthreads();
    {
        float a = rs[tid], b = rt[tid], c = bc;
        for (int o = 16; o; o >>= 1) {
            a += __shfl_down_sync(0xffffffffu, a, o);
            b += __shfl_down_sync(0xffffffffu, b, o);
            c += __shfl_down_sync(0xffffffffu, c, o);
        }
        if ((tid & 31) == 0) { red1[tid >> 5] = a; red2[tid >> 5] = b; redb[tid >> 5] = c; }
        __syncthreads();
        if (tid == 0) {
            float s1 = 0.f, s2 = 0.f, s3 = 0.f;
            #pragma unroll
            for (int i = 0; i < 16; ++i) { s1 += red1[i]; s2 += red2[i]; s3 += redb[i]; }
            s_sus = s1; s_sut = s2;
            g_bias[j] = s3 + bfs[j] + bft[j];
        }
        __syncthreads();
    }
    float sus = s_sus, sut = s_sut;
    {
        int l = tid;
        int lo = (l - 12 < 0) ? 0 : l - 12;
        int hi = (l + 12 > 511) ? 511 : l + 12;
        float bs = 0.f, bt = 0.f;
        for (int m = lo; m <= hi; ++m) {
            float cnt = 1.f;
            if (l == 0)   cnt = (float)(13 - m);
            if (l == 511) cnt = (float)(m - 498);
            bs += cnt * rs[m];
            bt += cnt * rt[m];
        }
        bs *= 0.04f; bt *= 0.04f;
        float ml = 0.f;
        if (l >= 499 && l <= 510) ml = 0.04f;
        if (l == 511)             ml = 0.52f;
        float coef0 = ml - (l == 511 ? 1.f : 0.f);
        float coef1 = -ml;
        g_B[j * KTOT + l]        = rs[l] - bs + sus * coef0;   // seasonal side
        g_B[(96 + j) * KTOT + l] = bt + sut * coef1;           // trend side
    }
    if (tid < 96) {
        int q = tid;
        int i, g, dim, qq; qmap(q % 48, i, g, dim, qq);
        float rv0 = 0.f, rv1 = 0.f;
        if (q < 48) {
            const float* rw = (i == 0) ? rws0 : (i == 1) ? rws1 : (i == 2) ? rws2 : rws3;
            rv0 = rw[j * dim + qq];
        } else {
            const float* rw = (i == 0) ? rwt0 : (i == 1) ? rwt1 : (i == 2) ? rwt2 : rwt3;
            rv1 = rw[j * dim + qq];
        }
        g_B[j * KTOT + 512 + q]        = rv0;
        g_B[(96 + j) * KTOT + 512 + q] = rv1;
    }
}

// ================= k_pgemm (validated fragment layout) =================
__global__ __launch_bounds__(128) void k_pgemm() {
    __shared__ float sA[32 * 96];
    __shared__ float sB[32][8];
    int tid = threadIdx.x;
    int tp = tid >> 2;
    int tc = tid & 3;
    int col0 = blockIdx.x * 8;
    const float* A = (col0 >= 512) ? g_Ar : g_Ax;
    float acc[3][2] = {};
    for (int jc = 0; jc < 6; ++jc) {
        __syncthreads();
        const float4* srcA = reinterpret_cast<const float4*>(A + jc * 32 * 96);
        #pragma unroll
        for (int i = 0; i < 6; ++i)
            reinterpret_cast<float4*>(sA)[tid + i * 128] = srcA[tid + i * 128];
        #pragma unroll
        for (int i = 0; i < 2; ++i) {
            int idx = tid + i * 128;
            int jj = idx >> 3, cc = idx & 7;
            sB[jj][cc] = g_B[(jc * 32 + jj) * KTOT + col0 + cc];
        }
        __syncthreads();
        #pragma unroll 8
        for (int jj = 0; jj < 32; ++jj) {
            float b0 = sB[jj][tc * 2], b1 = sB[jj][tc * 2 + 1];
            #pragma unroll
            for (int u = 0; u < 3; ++u) {
                float a = sA[jj * 96 + tp * 3 + u];
                acc[u][0] += a * b0;
                acc[u][1] += a * b1;
            }
        }
    }
    #pragma unroll
    for (int v = 0; v < 2; ++v) {
        int col = col0 + tc * 2 + v;
        float add = (col == 511) ? 1.f : 0.f;
        #pragma unroll
        for (int u = 0; u < 3; ++u) {
            float val = acc[u][v] + add;
            int p = tp * 3 + u;
            __half hv = __float2half(val);
            int lane = (p & 7) * 4 + ((col & 7) >> 1);
            int reg  = (col >> 3) & 1;
            long off = ((((long)(col >> 5) * 2 + ((col >> 4) & 1)) * 12 + (p >> 3)) * 32
                        + lane) * 8 + reg * 4 + (col & 1) * 2;
            *(uint16_t*)((char*)g_Bf + off) = __half_as_ushort(hv);
        }
    }
}

// ================= k_main: KC=64, fp32-accum, 192-col tiles, 12 warps =================
__global__ __launch_bounds__(384, 1) void k_main(
    const float* __restrict__ x, const float* __restrict__ rds,
    const float* __restrict__ rdt, const int* __restrict__ index,
    float* __restrict__ out) {
    __shared__ int sxb[COLS], sdb[COLS], sob[COLS];
    __shared__ const float* qptr[96];
    __shared__ float sbias[96];
    extern __shared__ char dsm_raw[];

    int tid = threadIdx.x;
    int wid = tid >> 5, lane = tid & 31;
    int j0 = blockIdx.x * COLS;

    if (tid < COLS) {
        int jj = j0 + tid;
        int b = jj / NCH, c = jj - b * NCH;
        sxb[tid] = b * SEQ * NCH + c;
        sob[tid] = b * PRED * NCH + c;
        sdb[tid] = index[b] * PRED * NCH + c;
    }
    if (tid < 96) {
        int q = tid;
        int i, g, dim, qq; qmap(q % 48, i, g, dim, qq);
        const float* base = (q < 48) ? rds : rdt;
        qptr[q] = base + (size_t)i * (NDICT * PRED * NCH) + (size_t)qq * g * NCH;
        sbias[tid] = g_bias[tid];
    }
    __syncthreads();

    uint32_t db = (uint32_t)__cvta_generic_to_shared(dsm_raw);
    uint32_t ab = (db + 127u) & ~127u;
    // A: 192 rows x 144B = 27648 per buffer, 3 buffers
    uint32_t AF[3] = { ab, ab + 27648, ab + 55296 };
    // B: 12288 per buffer (4 x 3072 k16-groups), 4 buffers
    uint32_t BF[4] = { ab + 82944, ab + 95232, ab + 107520, ab + 119808 };

    int m  = tid % COLS;         // producer column
    int kh = tid / COLS;         // 0/1: which 32-k half of the 64-k chunk
    const float* xcol = x + sxb[m];
    int dcol = sdb[m];
    uint32_t arow = (uint32_t)(m * 144 + kh * 64);

    int mw = wid & 3;            // m-group: rows mw*48 .. +47 (3 mtiles)
    int ng = wid >> 2;           // n-group: nt ng*4 .. +3
    uint32_t aoff[3];
    #pragma unroll
    for (int s = 0; s < 3; ++s)
        aoff[s] = (uint32_t)((mw * 48 + s * 16 + (lane & 7) + ((lane >> 3) & 1) * 8) * 144
                             + ((lane >> 4) & 1) * 16);
    uint32_t boff = (uint32_t)(ng * 4 * 256 + lane * 8);

    float facc[3][4][4];
    #pragma unroll
    for (int s = 0; s < 3; ++s)
        #pragma unroll
        for (int n = 0; n < 4; ++n)
            #pragma unroll
            for (int v = 0; v < 4; ++v) facc[s][n][v] = 0.f;

    float va[16], vb[16];

    #define LDGA(cc) do {                                                    \
        if (!((cc) == 9 && kh == 1)) {                                       \
            int _k0 = (cc) * KC + kh * 32;                                   \
            if (_k0 < 512) {                                                 \
                const float* _s = xcol + (size_t)_k0 * NCH;                  \
                _Pragma("unroll")                                            \
                for (int i_ = 0; i_ < 16; ++i_) va[i_] = _s[i_ * NCH];       \
                _s += 16 * NCH;                                              \
                _Pragma("unroll")                                            \
                for (int i_ = 0; i_ < 16; ++i_) vb[i_] = _s[i_ * NCH];       \
            } else {                                                         \
                int _q0 = _k0 - 512;                                         \
                _Pragma("unroll")                                            \
                for (int i_ = 0; i_ < 16; ++i_) va[i_] = qptr[_q0 + i_][dcol];\
                _Pragma("unroll")                                            \
                for (int i_ = 0; i_ < 16; ++i_) vb[i_] = qptr[_q0 + 16 + i_][dcol];\
            }                                                                \
        }                                                                    \
    } while (0)

    #define STSA(abuf) do {                                                  \
        uint32_t h_[8];                                                      \
        _Pragma("unroll")                                                    \
        for (int t_ = 0; t_ < 8; ++t_)                                       \
            h_[t_] = pack_f16x2(va[2 * t_], va[2 * t_ + 1]);                 \
        sts128(AF[abuf] + arow,      h_[0], h_[1], h_[2], h_[3]);            \
        sts128(AF[abuf] + arow + 16, h_[4], h_[5], h_[6], h_[7]);            \
        _Pragma("unroll")                                                    \
        for (int t_ = 0; t_ < 8; ++t_)                                       \
            h_[t_] = pack_f16x2(vb[2 * t_], vb[2 * t_ + 1]);                 \
        sts128(AF[abuf] + arow + 32, h_[0], h_[1], h_[2], h_[3]);            \
        sts128(AF[abuf] + arow + 48, h_[4], h_[5], h_[6], h_[7]);            \
    } while (0)

    #define FILLB(bbuf, cc) do {                                             \
        const char* _sf = (const char*)g_Bf + (size_t)(cc) * 12288;          \
        uint32_t off = (uint32_t)tid * 16u;                                  \
        cpa16(BF[bbuf] + off, _sf + off);                                    \
        if ((cc) < 9) cpa16(BF[bbuf] + off + 6144, _sf + off + 6144);        \
    } while (0)

    // prologue
    LDGA(0); STSA(0);
    LDGA(1);
    FILLB(0, 0); cp_commit();
    FILLB(1, 1); cp_commit();

    #pragma unroll 1
    for (int c = 0; c < NCHUNK; ++c) {
        int ac = c % 3;
        int bc = c & 3;
        if (c + 1 < NCHUNK) STSA((c + 1) % 3);      // va/vb hold chunk c+1
        if (c + 2 < NCHUNK) {
            LDGA(c + 2);
            FILLB((c + 2) & 3, c + 2);
        }
        cp_commit();
        cp_wait2();
        __syncthreads();

        int nkt = (c == 9) ? 2 : 4;
        #pragma unroll 1
        for (int kt = 0; kt < nkt; ++kt) {
            uint32_t a[3][4];
            #pragma unroll
            for (int s = 0; s < 3; ++s)
                ldmat4(a[s], AF[ac] + aoff[s] + kt * 32);
            uint32_t bb = BF[bc] + (uint32_t)(kt * 3072) + boff;
            #pragma unroll
            for (int n = 0; n < 4; ++n) {
                uint32_t b0, b1;
                lds64(b0, b1, bb + n * 256);
                #pragma unroll
                for (int s = 0; s < 3; ++s)
                    mma16816(facc[s][n], a[s], b0, b1);
            }
        }
    }
    #undef LDGA
    #undef STSA
    #undef FILLB

    // ---- epilogue ----
    int g = lane >> 2, tg = lane & 3;
    #pragma unroll
    for (int s = 0; s < 3; ++s) {
        int r0 = mw * 48 + s * 16 + g, r1 = r0 + 8;
        int ob0 = sob[r0], ob1 = sob[r1];
        #pragma unroll
        for (int n = 0; n < 4; ++n) {
            int p0 = (ng * 4 + n) * 8 + tg * 2;
            float sb0 = sbias[p0], sb1 = sbias[p0 + 1];
            out[ob0 + p0 * NCH]       = facc[s][n][0] + sb0;
            out[ob0 + (p0 + 1) * NCH] = facc[s][n][1] + sb1;
            out[ob1 + p0 * NCH]       = facc[s][n][2] + sb0;
            out[ob1 + (p0 + 1) * NCH] = facc[s][n][3] + sb1;
        }
    }
}

// ---------------- launch ----------------
#define DSM_BYTES (132096 + 256)

extern "C" void kernel_launch(void* const* d_in, const int* in_sizes, int n_in,
                              void* d_out, int out_size) {
    const float* x   = (const float*)d_in[0];
    const int*   idx = (const int*)d_in[1];
    const float* rds = (const float*)d_in[2];
    const float* rdt = (const float*)d_in[3];
    const float* wxs = (const float*)d_in[4];
    const float* bxs = (const float*)d_in[5];
    const float* wxt = (const float*)d_in[6];
    const float* bxt = (const float*)d_in[7];

    const float *wfs, *bfs, *wft, *bft;
    const float *rws[4], *rbs[4], *rwt[4], *rbt[4];

    if (in_sizes[8] == PRED * 2 * PRED) {
        wfs = (const float*)d_in[8];  bfs = (const float*)d_in[9];
        wft = (const float*)d_in[10]; bft = (const float*)d_in[11];
        for (int i = 0; i < 4; ++i) {
            rws[i] = (const float*)d_in[12 + 4 * i];
            rbs[i] = (const float*)d_in[13 + 4 * i];
            rwt[i] = (const float*)d_in[14 + 4 * i];
            rbt[i] = (const float*)d_in[15 + 4 * i];
        }
    } else {
        for (int i = 0; i < 4; ++i) {
            rws[i] = (const float*)d_in[8 + i];
            rbs[i] = (const float*)d_in[12 + i];
            rwt[i] = (const float*)d_in[16 + i];
            rbt[i] = (const float*)d_in[20 + i];
        }
        wfs = (const float*)d_in[24]; bfs = (const float*)d_in[25];
        wft = (const float*)d_in[26]; bft = (const float*)d_in[27];
    }

    float* out = (float*)d_out;

    cudaFuncSetAttribute(k_main, cudaFuncAttributeMaxDynamicSharedMemorySize,
                         DSM_BYTES);

    k_prep<<<100, 512>>>(wxs, wxt, wfs, wft,
                         rws[0], rws[1], rws[2], rws[3],
                         rwt[0], rwt[1], rwt[2], rwt[3],
                         bxs, bxt, bfs, bft,
                         rbs[0], rbs[1], rbs[2], rbs[3],
                         rbt[0], rbt[1], rbt[2], rbt[3]);
    k_pgemm<<<76, 128>>>();
    k_main<<<NTILES, 384, DSM_BYTES>>>(x, rds, rdt, idx, out);
}

// round 16
// speedup vs baseline: 1.4334x; 1.0652x over previous
#include <cuda_runtime.h>
#include <cuda_fp16.h>
#include <cstdint>

#define PRED  96
#define SEQ   512
#define NCH   321
#define NB    64
#define KTOT  608
#define NDICT 2000
#define NCOL  20544
#define KC    64
#define NCHUNK 10          // 9 x 64k + 1 x 32k
#define CMAX  144

// ---------------- device scratch ----------------
__device__ float g_bias[PRED];
__device__ float g_B[192 * KTOT];       // [j][col]
__device__ float g_Ax[192 * PRED];      // [j][p]
__device__ float g_Ar[192 * PRED];      // [j][p]
__device__ uint16_t g_Bf[19 * 3072];    // W fragments fp16 [k32grp][kt2][nt12][lane][reg2]

__device__ __forceinline__ void qmap(int q, int &i, int &g, int &dim, int &qq) {
    if (q < 24)      { i = 0; g = 4;  dim = 24; qq = q;      }
    else if (q < 36) { i = 1; g = 8;  dim = 12; qq = q - 24; }
    else if (q < 44) { i = 2; g = 12; dim = 8;  qq = q - 36; }
    else             { i = 3; g = 24; dim = 4;  qq = q - 44; }
}

// ---------------- asm helpers ----------------
__device__ __forceinline__ uint32_t pack_f16x2(float lo, float hi) {
    uint32_t r;
    asm("cvt.rn.f16x2.f32 %0, %1, %2;" : "=r"(r) : "f"(hi), "f"(lo));
    return r;
}
__device__ __forceinline__ void sts128(uint32_t a, uint32_t v0, uint32_t v1,
                                       uint32_t v2, uint32_t v3) {
    asm volatile("st.shared.v4.b32 [%0], {%1,%2,%3,%4};"
                 :: "r"(a), "r"(v0), "r"(v1), "r"(v2), "r"(v3));
}
__device__ __forceinline__ void cpa16(uint32_t d, const void* s) {
    asm volatile("cp.async.cg.shared.global [%0], [%1], 16;" :: "r"(d), "l"(s));
}
__device__ __forceinline__ void cp_commit() { asm volatile("cp.async.commit_group;"); }
__device__ __forceinline__ void cp_wait2()  { asm volatile("cp.async.wait_group 2;" ::: "memory"); }

__device__ __forceinline__ void ldmat4(uint32_t* a, uint32_t addr) {
    asm volatile("ldmatrix.sync.aligned.m8n8.x4.shared.b16 {%0,%1,%2,%3}, [%4];"
                 : "=r"(a[0]), "=r"(a[1]), "=r"(a[2]), "=r"(a[3]) : "r"(addr));
}
__device__ __forceinline__ void lds64(uint32_t &b0, uint32_t &b1, uint32_t addr) {
    asm volatile("ld.shared.v2.b32 {%0,%1}, [%2];" : "=r"(b0), "=r"(b1) : "r"(addr));
}
__device__ __forceinline__ void mma16816(float* d, const uint32_t* a,
                                         uint32_t b0, uint32_t b1) {
    asm volatile(
        "mma.sync.aligned.m16n8k16.row.col.f32.f16.f16.f32 "
        "{%0,%1,%2,%3}, {%4,%5,%6,%7}, {%8,%9}, {%0,%1,%2,%3};"
        : "+f"(d[0]), "+f"(d[1]), "+f"(d[2]), "+f"(d[3])
        : "r"(a[0]), "r"(a[1]), "r"(a[2]), "r"(a[3]), "r"(b0), "r"(b1));
}

// ================= k_prep: 100 blocks, one wave (validated R14) =================
__global__ void k_prep(const float* __restrict__ wxs, const float* __restrict__ wxt,
    const float* __restrict__ wfs, const float* __restrict__ wft,
    const float* __restrict__ rws0, const float* __restrict__ rws1,
    const float* __restrict__ rws2, const float* __restrict__ rws3,
    const float* __restrict__ rwt0, const float* __restrict__ rwt1,
    const float* __restrict__ rwt2, const float* __restrict__ rwt3,
    const float* __restrict__ bxs,  const float* __restrict__ bxt,
    const float* __restrict__ bfs,  const float* __restrict__ bft,
    const float* __restrict__ rbs0, const float* __restrict__ rbs1,
    const float* __restrict__ rbs2, const float* __restrict__ rbs3,
    const float* __restrict__ rbt0, const float* __restrict__ rbt1,
    const float* __restrict__ rbt2, const float* __restrict__ rbt3) {
    int tid = threadIdx.x;
    if (blockIdx.x >= 96) {
        __shared__ float sm[96][97];
        int b2 = blockIdx.x - 96;
        int side = b2 >> 1, half = b2 & 1;
        const float* wf = side ? wft : wfs;
        float* dst = half ? g_Ar : g_Ax;
        for (int idx = tid; idx < 96 * 96; idx += blockDim.x) {
            int p = idx / 96, r = idx - p * 96;
            sm[p][r] = wf[p * 192 + half * 96 + r];
        }
        __syncthreads();
        for (int idx = tid; idx < 96 * 96; idx += blockDim.x) {
            int r = idx / 96, p = idx - r * 96;
            dst[(side * 96 + r) * 96 + p] = sm[p][r];
        }
        return;
    }
    __shared__ float rs[512], rt[512];
    __shared__ float red1[16], red2[16], redb[16];
    __shared__ float s_sus, s_sut;
    int j = blockIdx.x;
    rs[tid] = wxs[j * SEQ + tid];
    rt[tid] = wxt[j * SEQ + tid];
    float bc = 0.f;
    if (tid < 96) {
        bc = wfs[j * 192 + tid] * bxs[tid] + wft[j * 192 + tid] * bxt[tid];
    } else if (tid < 192) {
        int t2 = tid - 96;
        bc = wfs[j * 192 + 96 + t2] * (rbs0[t2] + rbs1[t2] + rbs2[t2] + rbs3[t2])
           + wft[j * 192 + 96 + t2] * (rbt0[t2] + rbt1[t2] + rbt2[t2] + rbt3[t2]);
    }
    __syncthreads();
    {
        float a = rs[tid], b = rt[tid], c = bc;
        for (int o = 16; o; o >>= 1) {
            a += __shfl_down_sync(0xffffffffu, a, o);
            b += __shfl_down_sync(0xffffffffu, b, o);
            c += __shfl_down_sync(0xffffffffu, c, o);
        }
        if ((tid & 31) == 0) { red1[tid >> 5] = a; red2[tid >> 5] = b; redb[tid >> 5] = c; }
        __syncthreads();
        if (tid == 0) {
            float s1 = 0.f, s2 = 0.f, s3 = 0.f;
            #pragma unroll
            for (int i = 0; i < 16; ++i) { s1 += red1[i]; s2 += red2[i]; s3 += redb[i]; }
            s_sus = s1; s_sut = s2;
            g_bias[j] = s3 + bfs[j] + bft[j];
        }
        __syncthreads();
    }
    float sus = s_sus, sut = s_sut;
    {
        int l = tid;
        int lo = (l - 12 < 0) ? 0 : l - 12;
        int hi = (l + 12 > 511) ? 511 : l + 12;
        float bs = 0.f, bt = 0.f;
        for (int m = lo; m <= hi; ++m) {
            float cnt = 1.f;
            if (l == 0)   cnt = (float)(13 - m);
            if (l == 511) cnt = (float)(m - 498);
            bs += cnt * rs[m];
            bt += cnt * rt[m];
        }
        bs *= 0.04f; bt *= 0.04f;
        float ml = 0.f;
        if (l >= 499 && l <= 510) ml = 0.04f;
        if (l == 511)             ml = 0.52f;
        float coef0 = ml - (l == 511 ? 1.f : 0.f);
        float coef1 = -ml;
        g_B[j * KTOT + l]        = rs[l] - bs + sus * coef0;
        g_B[(96 + j) * KTOT + l] = bt + sut * coef1;
    }
    if (tid < 96) {
        int q = tid;
        int i, g, dim, qq; qmap(q % 48, i, g, dim, qq);
        float rv0 = 0.f, rv1 = 0.f;
        if (q < 48) {
            const float* rw = (i == 0) ? rws0 : (i == 1) ? rws1 : (i == 2) ? rws2 : rws3;
            rv0 = rw[j * dim + qq];
        } else {
            const float* rw = (i == 0) ? rwt0 : (i == 1) ? rwt1 : (i == 2) ? rwt2 : rwt3;
            rv1 = rw[j * dim + qq];
        }
        g_B[j * KTOT + 512 + q]        = rv0;
        g_B[(96 + j) * KTOT + 512 + q] = rv1;
    }
}

// ================= k_pgemm (validated fragment layout) =================
__global__ __launch_bounds__(128) void k_pgemm() {
    __shared__ float sA[32 * 96];
    __shared__ float sB[32][8];
    int tid = threadIdx.x;
    int tp = tid >> 2;
    int tc = tid & 3;
    int col0 = blockIdx.x * 8;
    const float* A = (col0 >= 512) ? g_Ar : g_Ax;
    float acc[3][2] = {};
    for (int jc = 0; jc < 6; ++jc) {
        __syncthreads();
        const float4* srcA = reinterpret_cast<const float4*>(A + jc * 32 * 96);
        #pragma unroll
        for (int i = 0; i < 6; ++i)
            reinterpret_cast<float4*>(sA)[tid + i * 128] = srcA[tid + i * 128];
        #pragma unroll
        for (int i = 0; i < 2; ++i) {
            int idx = tid + i * 128;
            int jj = idx >> 3, cc = idx & 7;
            sB[jj][cc] = g_B[(jc * 32 + jj) * KTOT + col0 + cc];
        }
        __syncthreads();
        #pragma unroll 8
        for (int jj = 0; jj < 32; ++jj) {
            float b0 = sB[jj][tc * 2], b1 = sB[jj][tc * 2 + 1];
            #pragma unroll
            for (int u = 0; u < 3; ++u) {
                float a = sA[jj * 96 + tp * 3 + u];
                acc[u][0] += a * b0;
                acc[u][1] += a * b1;
            }
        }
    }
    #pragma unroll
    for (int v = 0; v < 2; ++v) {
        int col = col0 + tc * 2 + v;
        float add = (col == 511) ? 1.f : 0.f;
        #pragma unroll
        for (int u = 0; u < 3; ++u) {
            float val = acc[u][v] + add;
            int p = tp * 3 + u;
            __half hv = __float2half(val);
            int lane = (p & 7) * 4 + ((col & 7) >> 1);
            int reg  = (col >> 3) & 1;
            long off = ((((long)(col >> 5) * 2 + ((col >> 4) & 1)) * 12 + (p >> 3)) * 32
                        + lane) * 8 + reg * 4 + (col & 1) * 2;
            *(uint16_t*)((char*)g_Bf + off) = __half_as_ushort(hv);
        }
    }
}

// ================= k_main worker: templated tile width =================
// CT cols; warps: NWM m-groups x NNG n-groups; MT mtiles/warp, NT ntiles/warp.
template<int CT, int NWM, int MT, int NNG, int NT>
__device__ __forceinline__ void gemm_worker(
    int j0, const float* __restrict__ x, const float* __restrict__ rds,
    const float* __restrict__ rdt, const int* __restrict__ index,
    float* __restrict__ out,
    int* sxb, int* sdb, int* sob, const float** qptr, float* sbias,
    char* dsm_raw) {
    int tid = threadIdx.x;
    int wid = tid >> 5, lane = tid & 31;

    if (tid < CT) {
        int jj = j0 + tid;
        int b = jj / NCH, c = jj - b * NCH;
        sxb[tid] = b * SEQ * NCH + c;
        sob[tid] = b * PRED * NCH + c;
        sdb[tid] = index[b] * PRED * NCH + c;
    }
    if (tid < 96) {
        int q = tid;
        int i, g, dim, qq; qmap(q % 48, i, g, dim, qq);
        const float* base = (q < 48) ? rds : rdt;
        qptr[q] = base + (size_t)i * (NDICT * PRED * NCH) + (size_t)qq * g * NCH;
        sbias[tid] = g_bias[tid];
    }
    __syncthreads();

    uint32_t db = (uint32_t)__cvta_generic_to_shared(dsm_raw);
    uint32_t ab = (db + 127u) & ~127u;
    const uint32_t ASZ = CT * 144;
    uint32_t AF[3] = { ab, ab + ASZ, ab + 2 * ASZ };
    uint32_t BF[4] = { ab + 3 * ASZ, ab + 3 * ASZ + 12288,
                       ab + 3 * ASZ + 24576, ab + 3 * ASZ + 36864 };

    // producer: threads < 2*CT; column m, 32-k half kh
    int m  = tid % CT;
    int kh = tid / CT;                 // 0,1 active; >=2 idle
    bool prod = (kh < 2);
    const float* xcol = x + sxb[m];
    int dcol = sdb[m];
    uint32_t arow = (uint32_t)(m * 144 + kh * 64);

    int mw = wid / NNG;                // m-group
    int ng = wid % NNG;                // n-group
    uint32_t aoff[MT];
    #pragma unroll
    for (int s = 0; s < MT; ++s)
        aoff[s] = (uint32_t)((mw * MT * 16 + s * 16 + (lane & 7) + ((lane >> 3) & 1) * 8) * 144
                             + ((lane >> 4) & 1) * 16);
    uint32_t boff = (uint32_t)(ng * NT * 256 + lane * 8);

    float facc[MT][NT][4];
    #pragma unroll
    for (int s = 0; s < MT; ++s)
        #pragma unroll
        for (int n = 0; n < NT; ++n)
            #pragma unroll
            for (int v = 0; v < 4; ++v) facc[s][n][v] = 0.f;

    float va[16], vb[16];

    #define LDGA(cc) do {                                                    \
        if (prod && !((cc) == 9 && kh == 1)) {                               \
            int _k0 = (cc) * KC + kh * 32;                                   \
            if (_k0 < 512) {                                                 \
                const float* _s = xcol + (size_t)_k0 * NCH;                  \
                _Pragma("unroll")                                            \
                for (int i_ = 0; i_ < 16; ++i_) va[i_] = _s[i_ * NCH];       \
                _s += 16 * NCH;                                              \
                _Pragma("unroll")                                            \
                for (int i_ = 0; i_ < 16; ++i_) vb[i_] = _s[i_ * NCH];       \
            } else {                                                         \
                int _q0 = _k0 - 512;                                         \
                _Pragma("unroll")                                            \
                for (int i_ = 0; i_ < 16; ++i_) va[i_] = qptr[_q0 + i_][dcol];\
                _Pragma("unroll")                                            \
                for (int i_ = 0; i_ < 16; ++i_) vb[i_] = qptr[_q0 + 16 + i_][dcol];\
            }                                                                \
        }                                                                    \
    } while (0)

    #define STSA(abuf) do {                                                  \
        if (prod) {                                                          \
            uint32_t h_[8];                                                  \
            _Pragma("unroll")                                                \
            for (int t_ = 0; t_ < 8; ++t_)                                   \
                h_[t_] = pack_f16x2(va[2 * t_], va[2 * t_ + 1]);             \
            sts128(AF[abuf] + arow,      h_[0], h_[1], h_[2], h_[3]);        \
            sts128(AF[abuf] + arow + 16, h_[4], h_[5], h_[6], h_[7]);        \
            _Pragma("unroll")                                                \
            for (int t_ = 0; t_ < 8; ++t_)                                   \
                h_[t_] = pack_f16x2(vb[2 * t_], vb[2 * t_ + 1]);             \
            sts128(AF[abuf] + arow + 32, h_[0], h_[1], h_[2], h_[3]);        \
            sts128(AF[abuf] + arow + 48, h_[4], h_[5], h_[6], h_[7]);        \
        }                                                                    \
    } while (0)

    #define FILLB(bbuf, cc) do {                                             \
        const char* _sf = (const char*)g_Bf + (size_t)(cc) * 12288;          \
        uint32_t off = (uint32_t)tid * 16u;                                  \
        cpa16(BF[bbuf] + off, _sf + off);                                    \
        if ((cc) < 9) cpa16(BF[bbuf] + off + 6144, _sf + off + 6144);        \
    } while (0)

    // prologue
    LDGA(0); STSA(0);
    LDGA(1);
    FILLB(0, 0); cp_commit();
    FILLB(1, 1); cp_commit();

    #pragma unroll 1
    for (int c = 0; c < NCHUNK; ++c) {
        int ac = c % 3;
        int bc = c & 3;
        if (c + 1 < NCHUNK) STSA((c + 1) % 3);
        if (c + 2 < NCHUNK) {
            LDGA(c + 2);
            FILLB((c + 2) & 3, c + 2);
        }
        cp_commit();
        cp_wait2();
        __syncthreads();

        int nkt = (c == 9) ? 2 : 4;
        #pragma unroll 1
        for (int kt = 0; kt < nkt; ++kt) {
            uint32_t a[MT][4];
            #pragma unroll
            for (int s = 0; s < MT; ++s)
                ldmat4(a[s], AF[ac] + aoff[s] + kt * 32);
            uint32_t bb = BF[bc] + (uint32_t)(kt * 3072) + boff;
            #pragma unroll
            for (int n = 0; n < NT; ++n) {
                uint32_t b0, b1;
                lds64(b0, b1, bb + n * 256);
                #pragma unroll
                for (int s = 0; s < MT; ++s)
                    mma16816(facc[s][n], a[s], b0, b1);
            }
        }
    }
    #undef LDGA
    #undef STSA
    #undef FILLB

    // ---- epilogue ----
    int g = lane >> 2, tg = lane & 3;
    #pragma unroll
    for (int s = 0; s < MT; ++s) {
        int r0 = mw * MT * 16 + s * 16 + g, r1 = r0 + 8;
        int ob0 = sob[r0], ob1 = sob[r1];
        #pragma unroll
        for (int n = 0; n < NT; ++n) {
            int p0 = (ng * NT + n) * 8 + tg * 2;
            float sb0 = sbias[p0], sb1 = sbias[p0 + 1];
            out[ob0 + p0 * NCH]       = facc[s][n][0] + sb0;
            out[ob0 + (p0 + 1) * NCH] = facc[s][n][1] + sb1;
            out[ob1 + p0 * NCH]       = facc[s][n][2] + sb0;
            out[ob1 + (p0 + 1) * NCH] = facc[s][n][3] + sb1;
        }
    }
}

// 148 CTAs: 100 x 144 cols + 48 x 128 cols = 20544 exact, one wave on 148 SMs.
__global__ __launch_bounds__(384, 1) void k_main(
    const float* __restrict__ x, const float* __restrict__ rds,
    const float* __restrict__ rdt, const int* __restrict__ index,
    float* __restrict__ out) {
    __shared__ int sxb[CMAX], sdb[CMAX], sob[CMAX];
    __shared__ const float* qptr[96];
    __shared__ float sbias[96];
    extern __shared__ char dsm_raw[];
    int bid = blockIdx.x;
    if (bid < 100) {
        gemm_worker<144, 3, 3, 4, 3>(bid * 144, x, rds, rdt, index, out,
                                     sxb, sdb, sob, qptr, sbias, dsm_raw);
    } else {
        gemm_worker<128, 4, 2, 3, 4>(14400 + (bid - 100) * 128, x, rds, rdt, index, out,
                                     sxb, sdb, sob, qptr, sbias, dsm_raw);
    }
}

// ---------------- launch ----------------
// dsm: 3 x (144*144) + 4 x 12288 = 62208 + 49152 = 111360 (+ alignment)
#define DSM_BYTES (111360 + 256)

extern "C" void kernel_launch(void* const* d_in, const int* in_sizes, int n_in,
                              void* d_out, int out_size) {
    const float* x   = (const float*)d_in[0];
    const int*   idx = (const int*)d_in[1];
    const float* rds = (const float*)d_in[2];
    const float* rdt = (const float*)d_in[3];
    const float* wxs = (const float*)d_in[4];
    const float* bxs = (const float*)d_in[5];
    const float* wxt = (const float*)d_in[6];
    const float* bxt = (const float*)d_in[7];

    const float *wfs, *bfs, *wft, *bft;
    const float *rws[4], *rbs[4], *rwt[4], *rbt[4];

    if (in_sizes[8] == PRED * 2 * PRED) {
        wfs = (const float*)d_in[8];  bfs = (const float*)d_in[9];
        wft = (const float*)d_in[10]; bft = (const float*)d_in[11];
        for (int i = 0; i < 4; ++i) {
            rws[i] = (const float*)d_in[12 + 4 * i];
            rbs[i] = (const float*)d_in[13 + 4 * i];
            rwt[i] = (const float*)d_in[14 + 4 * i];
            rbt[i] = (const float*)d_in[15 + 4 * i];
        }
    } else {
        for (int i = 0; i < 4; ++i) {
            rws[i] = (const float*)d_in[8 + i];
            rbs[i] = (const float*)d_in[12 + i];
            rwt[i] = (const float*)d_in[16 + i];
            rbt[i] = (const float*)d_in[20 + i];
        }
        wfs = (const float*)d_in[24]; bfs = (const float*)d_in[25];
        wft = (const float*)d_in[26]; bft = (const float*)d_in[27];
    }

    float* out = (float*)d_out;

    cudaFuncSetAttribute(k_main, cudaFuncAttributeMaxDynamicSharedMemorySize,
                         DSM_BYTES);

    k_prep<<<100, 512>>>(wxs, wxt, wfs, wft,
                         rws[0], rws[1], rws[2], rws[3],
                         rwt[0], rwt[1], rwt[2], rwt[3],
                         bxs, bxt, bfs, bft,
                         rbs[0], rbs[1], rbs[2], rbs[3],
                         rbt[0], rbt[1], rbt[2], rbt[3]);
    k_pgemm<<<76, 128>>>();
    k_main<<<148, 384, DSM_BYTES>>>(x, rds, rdt, idx, out);
}

// round 17
// speedup vs baseline: 1.5412x; 1.0753x over previous
#include <cuda_runtime.h>
#include <cuda_fp16.h>
#include <cstdint>

#define PRED  96
#define SEQ   512
#define NCH   321
#define NB    64
#define KTOT  608
#define NDICT 2000
#define NCOL  20544
#define KC    64
#define NCHUNK 10          // 9 x 64k + 1 x 32k
#define CMAX  144
#define NCTA  148

// ---------------- device scratch ----------------
__device__ float g_bias[PRED];
__device__ float g_B[192 * KTOT];       // [j][col]
__device__ float g_Ax[192 * PRED];      // [j][p]
__device__ float g_Ar[192 * PRED];      // [j][p]
__device__ uint16_t g_Bf[19 * 3072];    // W fragments fp16
__device__ unsigned g_bar1, g_bar2;     // monotonic grid barriers (replay-safe)

__device__ __forceinline__ void qmap(int q, int &i, int &g, int &dim, int &qq) {
    if (q < 24)      { i = 0; g = 4;  dim = 24; qq = q;      }
    else if (q < 36) { i = 1; g = 8;  dim = 12; qq = q - 24; }
    else if (q < 44) { i = 2; g = 12; dim = 8;  qq = q - 36; }
    else             { i = 3; g = 24; dim = 4;  qq = q - 44; }
}

// ---------------- asm helpers ----------------
__device__ __forceinline__ uint32_t pack_f16x2(float lo, float hi) {
    uint32_t r;
    asm("cvt.rn.f16x2.f32 %0, %1, %2;" : "=r"(r) : "f"(hi), "f"(lo));
    return r;
}
__device__ __forceinline__ void sts128(uint32_t a, uint32_t v0, uint32_t v1,
                                       uint32_t v2, uint32_t v3) {
    asm volatile("st.shared.v4.b32 [%0], {%1,%2,%3,%4};"
                 :: "r"(a), "r"(v0), "r"(v1), "r"(v2), "r"(v3));
}
__device__ __forceinline__ void cpa16(uint32_t d, const void* s) {
    asm volatile("cp.async.cg.shared.global [%0], [%1], 16;" :: "r"(d), "l"(s));
}
__device__ __forceinline__ void cp_commit() { asm volatile("cp.async.commit_group;"); }
__device__ __forceinline__ void cp_wait2()  { asm volatile("cp.async.wait_group 2;" ::: "memory"); }

__device__ __forceinline__ void ldmat4(uint32_t* a, uint32_t addr) {
    asm volatile("ldmatrix.sync.aligned.m8n8.x4.shared.b16 {%0,%1,%2,%3}, [%4];"
                 : "=r"(a[0]), "=r"(a[1]), "=r"(a[2]), "=r"(a[3]) : "r"(addr));
}
__device__ __forceinline__ void lds64(uint32_t &b0, uint32_t &b1, uint32_t addr) {
    asm volatile("ld.shared.v2.b32 {%0,%1}, [%2];" : "=r"(b0), "=r"(b1) : "r"(addr));
}
__device__ __forceinline__ void mma16816(float* d, const uint32_t* a,
                                         uint32_t b0, uint32_t b1) {
    asm volatile(
        "mma.sync.aligned.m16n8k16.row.col.f32.f16.f16.f32 "
        "{%0,%1,%2,%3}, {%4,%5,%6,%7}, {%8,%9}, {%0,%1,%2,%3};"
        : "+f"(d[0]), "+f"(d[1]), "+f"(d[2]), "+f"(d[3])
        : "r"(a[0]), "r"(a[1]), "r"(a[2]), "r"(a[3]), "r"(b0), "r"(b1));
}

// monotonic grid barrier: safe across graph replays (no reset needed).
__device__ __forceinline__ void grid_barrier(unsigned* bar) {
    __syncthreads();
    if (threadIdx.x == 0) {
        __threadfence();
        unsigned a = atomicAdd(bar, 1u);
        unsigned target = (a / NCTA + 1u) * NCTA;
        unsigned v;
        do {
            asm volatile("ld.acquire.gpu.global.u32 %0, [%1];"
                         : "=r"(v) : "l"(bar) : "memory");
        } while (v < target);
    }
    __syncthreads();
}

// ================= gemm worker (validated R16) =================
template<int CT, int NWM, int MT, int NNG, int NT>
__device__ __forceinline__ void gemm_worker(
    int j0, const float* __restrict__ x, const float* __restrict__ rds,
    const float* __restrict__ rdt, const int* __restrict__ index,
    float* __restrict__ out,
    int* sxb, int* sdb, int* sob, const float** qptr, float* sbias,
    char* dsm_raw) {
    int tid = threadIdx.x;
    int wid = tid >> 5, lane = tid & 31;

    if (tid < CT) {
        int jj = j0 + tid;
        int b = jj / NCH, c = jj - b * NCH;
        sxb[tid] = b * SEQ * NCH + c;
        sob[tid] = b * PRED * NCH + c;
        sdb[tid] = index[b] * PRED * NCH + c;
    }
    if (tid < 96) {
        int q = tid;
        int i, g, dim, qq; qmap(q % 48, i, g, dim, qq);
        const float* base = (q < 48) ? rds : rdt;
        qptr[q] = base + (size_t)i * (NDICT * PRED * NCH) + (size_t)qq * g * NCH;
        sbias[tid] = g_bias[tid];
    }
    __syncthreads();

    uint32_t db = (uint32_t)__cvta_generic_to_shared(dsm_raw);
    uint32_t ab = (db + 127u) & ~127u;
    const uint32_t ASZ = CT * 144;
    uint32_t AF[3] = { ab, ab + ASZ, ab + 2 * ASZ };
    uint32_t BF[4] = { ab + 3 * ASZ, ab + 3 * ASZ + 12288,
                       ab + 3 * ASZ + 24576, ab + 3 * ASZ + 36864 };

    int m  = tid % CT;
    int kh = tid / CT;
    bool prod = (kh < 2);
    const float* xcol = x + sxb[m];
    int dcol = sdb[m];
    uint32_t arow = (uint32_t)(m * 144 + kh * 64);

    int mw = wid / NNG;
    int ng = wid % NNG;
    uint32_t aoff[MT];
    #pragma unroll
    for (int s = 0; s < MT; ++s)
        aoff[s] = (uint32_t)((mw * MT * 16 + s * 16 + (lane & 7) + ((lane >> 3) & 1) * 8) * 144
                             + ((lane >> 4) & 1) * 16);
    uint32_t boff = (uint32_t)(ng * NT * 256 + lane * 8);

    float facc[MT][NT][4];
    #pragma unroll
    for (int s = 0; s < MT; ++s)
        #pragma unroll
        for (int n = 0; n < NT; ++n)
            #pragma unroll
            for (int v = 0; v < 4; ++v) facc[s][n][v] = 0.f;

    float va[16], vb[16];

    #define LDGA(cc) do {                                                    \
        if (prod && !((cc) == 9 && kh == 1)) {                               \
            int _k0 = (cc) * KC + kh * 32;                                   \
            if (_k0 < 512) {                                                 \
                const float* _s = xcol + (size_t)_k0 * NCH;                  \
                _Pragma("unroll")                                            \
                for (int i_ = 0; i_ < 16; ++i_) va[i_] = _s[i_ * NCH];       \
                _s += 16 * NCH;                                              \
                _Pragma("unroll")                                            \
                for (int i_ = 0; i_ < 16; ++i_) vb[i_] = _s[i_ * NCH];       \
            } else {                                                         \
                int _q0 = _k0 - 512;                                         \
                _Pragma("unroll")                                            \
                for (int i_ = 0; i_ < 16; ++i_) va[i_] = qptr[_q0 + i_][dcol];\
                _Pragma("unroll")                                            \
                for (int i_ = 0; i_ < 16; ++i_) vb[i_] = qptr[_q0 + 16 + i_][dcol];\
            }                                                                \
        }                                                                    \
    } while (0)

    #define STSA(abuf) do {                                                  \
        if (prod) {                                                          \
            uint32_t h_[8];                                                  \
            _Pragma("unroll")                                                \
            for (int t_ = 0; t_ < 8; ++t_)                                   \
                h_[t_] = pack_f16x2(va[2 * t_], va[2 * t_ + 1]);             \
            sts128(AF[abuf] + arow,      h_[0], h_[1], h_[2], h_[3]);        \
            sts128(AF[abuf] + arow + 16, h_[4], h_[5], h_[6], h_[7]);        \
            _Pragma("unroll")                                                \
            for (int t_ = 0; t_ < 8; ++t_)                                   \
                h_[t_] = pack_f16x2(vb[2 * t_], vb[2 * t_ + 1]);             \
            sts128(AF[abuf] + arow + 32, h_[0], h_[1], h_[2], h_[3]);        \
            sts128(AF[abuf] + arow + 48, h_[4], h_[5], h_[6], h_[7]);        \
        }                                                                    \
    } while (0)

    #define FILLB(bbuf, cc) do {                                             \
        const char* _sf = (const char*)g_Bf + (size_t)(cc) * 12288;          \
        uint32_t off = (uint32_t)tid * 16u;                                  \
        cpa16(BF[bbuf] + off, _sf + off);                                    \
        if ((cc) < 9) cpa16(BF[bbuf] + off + 6144, _sf + off + 6144);        \
    } while (0)

    LDGA(0); STSA(0);
    LDGA(1);
    FILLB(0, 0); cp_commit();
    FILLB(1, 1); cp_commit();

    #pragma unroll 1
    for (int c = 0; c < NCHUNK; ++c) {
        int ac = c % 3;
        int bc = c & 3;
        if (c + 1 < NCHUNK) STSA((c + 1) % 3);
        if (c + 2 < NCHUNK) {
            LDGA(c + 2);
            FILLB((c + 2) & 3, c + 2);
        }
        cp_commit();
        cp_wait2();
        __syncthreads();

        int nkt = (c == 9) ? 2 : 4;
        #pragma unroll 1
        for (int kt = 0; kt < nkt; ++kt) {
            uint32_t a[MT][4];
            #pragma unroll
            for (int s = 0; s < MT; ++s)
                ldmat4(a[s], AF[ac] + aoff[s] + kt * 32);
            uint32_t bb = BF[bc] + (uint32_t)(kt * 3072) + boff;
            #pragma unroll
            for (int n = 0; n < NT; ++n) {
                uint32_t b0, b1;
                lds64(b0, b1, bb + n * 256);
                #pragma unroll
                for (int s = 0; s < MT; ++s)
                    mma16816(facc[s][n], a[s], b0, b1);
            }
        }
    }
    #undef LDGA
    #undef STSA
    #undef FILLB

    int g = lane >> 2, tg = lane & 3;
    #pragma unroll
    for (int s = 0; s < MT; ++s) {
        int r0 = mw * MT * 16 + s * 16 + g, r1 = r0 + 8;
        int ob0 = sob[r0], ob1 = sob[r1];
        #pragma unroll
        for (int n = 0; n < NT; ++n) {
            int p0 = (ng * NT + n) * 8 + tg * 2;
            float sb0 = sbias[p0], sb1 = sbias[p0 + 1];
            out[ob0 + p0 * NCH]       = facc[s][n][0] + sb0;
            out[ob0 + (p0 + 1) * NCH] = facc[s][n][1] + sb1;
            out[ob1 + p0 * NCH]       = facc[s][n][2] + sb0;
            out[ob1 + (p0 + 1) * NCH] = facc[s][n][3] + sb1;
        }
    }
}

// ================= fused kernel =================
__global__ __launch_bounds__(384, 1) void k_all(
    const float* __restrict__ x, const float* __restrict__ rds,
    const float* __restrict__ rdt, const int* __restrict__ index,
    float* __restrict__ out,
    const float* __restrict__ wxs, const float* __restrict__ wxt,
    const float* __restrict__ wfs, const float* __restrict__ wft,
    const float* __restrict__ rws0, const float* __restrict__ rws1,
    const float* __restrict__ rws2, const float* __restrict__ rws3,
    const float* __restrict__ rwt0, const float* __restrict__ rwt1,
    const float* __restrict__ rwt2, const float* __restrict__ rwt3,
    const float* __restrict__ bxs,  const float* __restrict__ bxt,
    const float* __restrict__ bfs,  const float* __restrict__ bft,
    const float* __restrict__ rbs0, const float* __restrict__ rbs1,
    const float* __restrict__ rbs2, const float* __restrict__ rbs3,
    const float* __restrict__ rbt0, const float* __restrict__ rbt1,
    const float* __restrict__ rbt2, const float* __restrict__ rbt3) {
    __shared__ int sxb[CMAX], sdb[CMAX], sob[CMAX];
    __shared__ const float* qptr[96];
    __shared__ float sbias[96];
    __shared__ float red1[12], red2[12], redb[12];
    __shared__ float s_sus, s_sut;
    extern __shared__ char dsm_raw[];

    int tid = threadIdx.x;
    int bid = blockIdx.x;

    // ---------- Phase A: band rows + bias (CTAs 0..95), wf transpose (96..99) ----------
    if (bid < 96) {
        float* rs = (float*)dsm_raw;        // 512 floats
        float* rt = rs + 512;
        int j = bid;
        for (int l = tid; l < 512; l += 384) {
            rs[l] = wxs[j * SEQ + l];
            rt[l] = wxt[j * SEQ + l];
        }
        float bc = 0.f;
        if (tid < 96) {
            bc = wfs[j * 192 + tid] * bxs[tid] + wft[j * 192 + tid] * bxt[tid];
        } else if (tid < 192) {
            int t2 = tid - 96;
            bc = wfs[j * 192 + 96 + t2] * (rbs0[t2] + rbs1[t2] + rbs2[t2] + rbs3[t2])
               + wft[j * 192 + 96 + t2] * (rbt0[t2] + rbt1[t2] + rbt2[t2] + rbt3[t2]);
        }
        __syncthreads();
        {
            float a = 0.f, b = 0.f;
            for (int l = tid; l < 512; l += 384) { a += rs[l]; b += rt[l]; }
            float c = bc;
            for (int o = 16; o; o >>= 1) {
                a += __shfl_down_sync(0xffffffffu, a, o);
                b += __shfl_down_sync(0xffffffffu, b, o);
                c += __shfl_down_sync(0xffffffffu, c, o);
            }
            if ((tid & 31) == 0) { red1[tid >> 5] = a; red2[tid >> 5] = b; redb[tid >> 5] = c; }
            __syncthreads();
            if (tid == 0) {
                float s1 = 0.f, s2 = 0.f, s3 = 0.f;
                #pragma unroll
                for (int i = 0; i < 12; ++i) { s1 += red1[i]; s2 += red2[i]; s3 += redb[i]; }
                s_sus = s1; s_sut = s2;
                g_bias[j] = s3 + bfs[j] + bft[j];
            }
            __syncthreads();
        }
        float sus = s_sus, sut = s_sut;
        for (int l = tid; l < 512; l += 384) {
            int lo = (l - 12 < 0) ? 0 : l - 12;
            int hi = (l + 12 > 511) ? 511 : l + 12;
            float bs = 0.f, bt = 0.f;
            for (int m = lo; m <= hi; ++m) {
                float cnt = 1.f;
                if (l == 0)   cnt = (float)(13 - m);
                if (l == 511) cnt = (float)(m - 498);
                bs += cnt * rs[m];
                bt += cnt * rt[m];
            }
            bs *= 0.04f; bt *= 0.04f;
            float ml = 0.f;
            if (l >= 499 && l <= 510) ml = 0.04f;
            if (l == 511)             ml = 0.52f;
            float coef0 = ml - (l == 511 ? 1.f : 0.f);
            float coef1 = -ml;
            g_B[j * KTOT + l]        = rs[l] - bs + sus * coef0;
            g_B[(96 + j) * KTOT + l] = bt + sut * coef1;
        }
        if (tid < 96) {
            int q = tid;
            int i, g, dim, qq; qmap(q % 48, i, g, dim, qq);
            float rv0 = 0.f, rv1 = 0.f;
            if (q < 48) {
                const float* rw = (i == 0) ? rws0 : (i == 1) ? rws1 : (i == 2) ? rws2 : rws3;
                rv0 = rw[j * dim + qq];
            } else {
                const float* rw = (i == 0) ? rwt0 : (i == 1) ? rwt1 : (i == 2) ? rwt2 : rwt3;
                rv1 = rw[j * dim + qq];
            }
            g_B[j * KTOT + 512 + q]        = rv0;
            g_B[(96 + j) * KTOT + 512 + q] = rv1;
        }
    } else if (bid < 100) {
        float (*sm)[97] = (float(*)[97])dsm_raw;   // 96x97 floats
        int b2 = bid - 96;
        int side = b2 >> 1, half = b2 & 1;
        const float* wf = side ? wft : wfs;
        float* dst = half ? g_Ar : g_Ax;
        for (int idx = tid; idx < 96 * 96; idx += 384) {
            int p = idx / 96, r = idx - p * 96;
            sm[p][r] = wf[p * 192 + half * 96 + r];
        }
        __syncthreads();
        for (int idx = tid; idx < 96 * 96; idx += 384) {
            int r = idx / 96, p = idx - r * 96;
            dst[(side * 96 + r) * 96 + p] = sm[p][r];
        }
    }

    grid_barrier(&g_bar1);

    // ---------- Phase B: pgemm (CTAs 0..75, threads 0..127 active) ----------
    if (bid < 76) {
        float* sA = (float*)dsm_raw;               // 32*96
        float (*sB)[8] = (float(*)[8])(sA + 32 * 96);
        int col0 = bid * 8;
        const float* A = (col0 >= 512) ? g_Ar : g_Ax;
        bool act = tid < 128;
        int tp = tid >> 2, tc = tid & 3;
        float acc[3][2] = {};
        for (int jc = 0; jc < 6; ++jc) {
            __syncthreads();
            if (act) {
                const float4* srcA = reinterpret_cast<const float4*>(A + jc * 32 * 96);
                #pragma unroll
                for (int i = 0; i < 6; ++i)
                    reinterpret_cast<float4*>(sA)[tid + i * 128] = srcA[tid + i * 128];
                #pragma unroll
                for (int i = 0; i < 2; ++i) {
                    int idx = tid + i * 128;
                    int jj = idx >> 3, cc = idx & 7;
                    sB[jj][cc] = g_B[(jc * 32 + jj) * KTOT + col0 + cc];
                }
            }
            __syncthreads();
            if (act) {
                #pragma unroll 8
                for (int jj = 0; jj < 32; ++jj) {
                    float b0 = sB[jj][tc * 2], b1 = sB[jj][tc * 2 + 1];
                    #pragma unroll
                    for (int u = 0; u < 3; ++u) {
                        float a = sA[jj * 96 + tp * 3 + u];
                        acc[u][0] += a * b0;
                        acc[u][1] += a * b1;
                    }
                }
            }
        }
        if (act) {
            #pragma unroll
            for (int v = 0; v < 2; ++v) {
                int col = col0 + tc * 2 + v;
                float add = (col == 511) ? 1.f : 0.f;
                #pragma unroll
                for (int u = 0; u < 3; ++u) {
                    float val = acc[u][v] + add;
                    int p = tp * 3 + u;
                    __half hv = __float2half(val);
                    int lane = (p & 7) * 4 + ((col & 7) >> 1);
                    int reg  = (col >> 3) & 1;
                    long off = ((((long)(col >> 5) * 2 + ((col >> 4) & 1)) * 12 + (p >> 3)) * 32
                                + lane) * 8 + reg * 4 + (col & 1) * 2;
                    *(uint16_t*)((char*)g_Bf + off) = __half_as_ushort(hv);
                }
            }
        }
    }

    grid_barrier(&g_bar2);

    // ---------- Phase C: main GEMM (all 148 CTAs) ----------
    if (bid < 100) {
        gemm_worker<144, 3, 3, 4, 3>(bid * 144, x, rds, rdt, index, out,
                                     sxb, sdb, sob, qptr, sbias, dsm_raw);
    } else {
        gemm_worker<128, 4, 2, 3, 4>(14400 + (bid - 100) * 128, x, rds, rdt, index, out,
                                     sxb, sdb, sob, qptr, sbias, dsm_raw);
    }
}

// ---------------- launch ----------------
// dsm: 3 x (144*144) + 4 x 12288 = 111360 (+ alignment)
#define DSM_BYTES (111360 + 256)

extern "C" void kernel_launch(void* const* d_in, const int* in_sizes, int n_in,
                              void* d_out, int out_size) {
    const float* x   = (const float*)d_in[0];
    const int*   idx = (const int*)d_in[1];
    const float* rds = (const float*)d_in[2];
    const float* rdt = (const float*)d_in[3];
    const float* wxs = (const float*)d_in[4];
    const float* bxs = (const float*)d_in[5];
    const float* wxt = (const float*)d_in[6];
    const float* bxt = (const float*)d_in[7];

    const float *wfs, *bfs, *wft, *bft;
    const float *rws[4], *rbs[4], *rwt[4], *rbt[4];

    if (in_sizes[8] == PRED * 2 * PRED) {
        wfs = (const float*)d_in[8];  bfs = (const float*)d_in[9];
        wft = (const float*)d_in[10]; bft = (const float*)d_in[11];
        for (int i = 0; i < 4; ++i) {
            rws[i] = (const float*)d_in[12 + 4 * i];
            rbs[i] = (const float*)d_in[13 + 4 * i];
            rwt[i] = (const float*)d_in[14 + 4 * i];
            rbt[i] = (const float*)d_in[15 + 4 * i];
        }
    } else {
        for (int i = 0; i < 4; ++i) {
            rws[i] = (const float*)d_in[8 + i];
            rbs[i] = (const float*)d_in[12 + i];
            rwt[i] = (const float*)d_in[16 + i];
            rbt[i] = (const float*)d_in[20 + i];
        }
        wfs = (const float*)d_in[24]; bfs = (const float*)d_in[25];
        wft = (const float*)d_in[26]; bft = (const float*)d_in[27];
    }

    float* out = (float*)d_out;

    cudaFuncSetAttribute(k_all, cudaFuncAttributeMaxDynamicSharedMemorySize,
                         DSM_BYTES);

    k_all<<<NCTA, 384, DSM_BYTES>>>(x, rds, rdt, idx, out,
                                    wxs, wxt, wfs, wft,
                                    rws[0], rws[1], rws[2], rws[3],
                                    rwt[0], rwt[1], rwt[2], rwt[3],
                                    bxs, bxt, bfs, bft,
                                    rbs[0], rbs[1], rbs[2], rbs[3],
                                    rbt[0], rbt[1], rbt[2], rbt[3]);
}